// round 1
// baseline (speedup 1.0000x reference)
#include <cuda_runtime.h>
#include <math.h>
#include <cuda_bf16.h>

// ---------------- problem constants ----------------
static const int NN   = 50000;   // nodes
static const int EE   = 400000;  // edges
static const int FIN  = 64;
static const int EIN  = 16;
static const int HH   = 128;
static const int LL   = 4;
static const int GG   = 256;
static const int OUTC = 12;

// ---------------- scratch (static device globals; no runtime alloc) ----------------
__device__ float d_e0p[(size_t)EE * HH];        // permuted edge embedding (CSR order)
__device__ float d_mE [(size_t)EE * HH];        // per-edge message (edge part), CSR order
__device__ float d_pre[(size_t)NN * 2 * HH];    // [hd | hs]
__device__ float d_agg[(size_t)NN * 4 * HH];    // [mean|min|max|std]
__device__ float d_y  [(size_t)NN * 3 * HH];    // agg @ Qcat
__device__ float d_z  [(size_t)NN * HH];        // h @ Q0
__device__ float d_h0 [(size_t)NN * HH];
__device__ float d_h1 [(size_t)NN * HH];
__device__ int   d_deg [NN];
__device__ int   d_offs[NN + 1];
__device__ int   d_cnt [NN];
__device__ int   d_perm[EE];
__device__ int   d_srcp[EE];
__device__ float d_amp[NN];
__device__ float d_att[NN];
__device__ float d_avg[1];
__device__ float d_R   [LL * HH * HH];          // Wenc @ Wpre2
__device__ float d_rb  [LL * HH];               // benc@Wpre2 + pre_b
__device__ float d_Qcat[LL * 4 * HH * 3 * HH];  // [512,384] per layer: [P1|P2|P3]@lin
__device__ float d_Q0  [LL * HH * HH];          // P0@lin
__device__ float d_b2  [LL * HH];               // post_b@lin + lin_b
__device__ float d_g   [GG * HH];

// ---------------- generic fp32 SGEMM: C[M,N] = A[M,K] @ B[K,N] (+bias), opt A-row gather ----------------
// BM=BN=128, BK=8, 256 threads, 8x8 per thread. Requires K%8==0, N%128==0, 16B-aligned ptrs.
__global__ void __launch_bounds__(256) sgemm_kernel(
    const float* __restrict__ A, int lda,
    const float* __restrict__ B, int ldb,
    float* __restrict__ C, int ldc,
    int M, int N, int K,
    const float* __restrict__ bias,
    const int* __restrict__ perm)
{
    const int BM = 128, BN = 128, BK = 8;
    __shared__ float As[BK][BM];
    __shared__ float Bs[BK][BN];

    int tid  = threadIdx.x;
    int brow = blockIdx.y, bcol = blockIdx.x;

    int aRow  = tid >> 1;           // 0..127
    int aCol4 = (tid & 1) * 4;      // 0 or 4
    int bRow  = tid >> 5;           // 0..7
    int bCol4 = (tid & 31) * 4;     // 0..124

    int tr = (tid >> 4) * 8;        // 0..120
    int tc = (tid & 15) * 8;        // 0..120

    float acc[8][8];
#pragma unroll
    for (int i = 0; i < 8; i++)
#pragma unroll
        for (int j = 0; j < 8; j++) acc[i][j] = 0.f;

    int gArow = brow * BM + aRow;
    bool aValid = gArow < M;
    long arow_idx = 0;
    if (aValid) arow_idx = perm ? (long)perm[gArow] : (long)gArow;
    const float* Aptr = A + arow_idx * (long)lda + aCol4;
    const float* Bptr = B + (long)bRow * ldb + (long)bcol * BN + bCol4;

    for (int k0 = 0; k0 < K; k0 += BK) {
        float4 av = aValid ? *(const float4*)(Aptr + k0) : make_float4(0.f, 0.f, 0.f, 0.f);
        float4 bv = *(const float4*)(Bptr + (long)k0 * ldb);
        As[aCol4 + 0][aRow] = av.x;
        As[aCol4 + 1][aRow] = av.y;
        As[aCol4 + 2][aRow] = av.z;
        As[aCol4 + 3][aRow] = av.w;
        *(float4*)&Bs[bRow][bCol4] = bv;
        __syncthreads();
#pragma unroll
        for (int kk = 0; kk < BK; kk++) {
            float ar[8], br[8];
#pragma unroll
            for (int i = 0; i < 8; i++) ar[i] = As[kk][tr + i];
#pragma unroll
            for (int j = 0; j < 8; j++) br[j] = Bs[kk][tc + j];
#pragma unroll
            for (int i = 0; i < 8; i++)
#pragma unroll
                for (int j = 0; j < 8; j++)
                    acc[i][j] = fmaf(ar[i], br[j], acc[i][j]);
        }
        __syncthreads();
    }

#pragma unroll
    for (int i = 0; i < 8; i++) {
        int row = brow * BM + tr + i;
        if (row < M) {
#pragma unroll
            for (int j = 0; j < 8; j += 4) {
                int col = bcol * BN + tc + j;
                float4 v;
                v.x = acc[i][j + 0] + (bias ? bias[col + 0] : 0.f);
                v.y = acc[i][j + 1] + (bias ? bias[col + 1] : 0.f);
                v.z = acc[i][j + 2] + (bias ? bias[col + 2] : 0.f);
                v.w = acc[i][j + 3] + (bias ? bias[col + 3] : 0.f);
                *(float4*)&C[(long)row * ldc + col] = v;
            }
        }
    }
}

// ---------------- small helper kernels ----------------
__global__ void count_kernel(const int* __restrict__ dst, int n) {
    int i = blockIdx.x * blockDim.x + threadIdx.x;
    if (i < n) atomicAdd(&d_deg[dst[i]], 1);
}

// single-block exclusive scan of d_deg[0..NN) -> d_offs[0..NN]
__global__ void scan_kernel() {
    __shared__ int sh[1024];
    __shared__ int carry;
    if (threadIdx.x == 0) carry = 0;
    __syncthreads();
    for (int base = 0; base < NN; base += 1024) {
        int i = base + (int)threadIdx.x;
        int v = (i < NN) ? d_deg[i] : 0;
        sh[threadIdx.x] = v;
        __syncthreads();
        for (int off = 1; off < 1024; off <<= 1) {
            int t = (threadIdx.x >= (unsigned)off) ? sh[threadIdx.x - off] : 0;
            __syncthreads();
            sh[threadIdx.x] += t;
            __syncthreads();
        }
        if (i < NN) d_offs[i] = carry + sh[threadIdx.x] - v;
        __syncthreads();
        if (threadIdx.x == 1023) carry += sh[1023];
        __syncthreads();
    }
    if (threadIdx.x == 0) d_offs[NN] = carry;
}

__global__ void scatter_kernel(const int* __restrict__ src, const int* __restrict__ dst, int n) {
    int i = blockIdx.x * blockDim.x + threadIdx.x;
    if (i < n) {
        int pos = atomicAdd(&d_cnt[dst[i]], 1);
        d_perm[pos] = i;
        d_srcp[pos] = src[i];
    }
}

__global__ void logdeg_sum_kernel() {
    __shared__ float sh[256];
    float s = 0.f;
    for (int i = blockIdx.x * blockDim.x + threadIdx.x; i < NN; i += gridDim.x * blockDim.x)
        s += log1pf((float)d_deg[i]);
    sh[threadIdx.x] = s;
    __syncthreads();
    for (int off = 128; off > 0; off >>= 1) {
        if (threadIdx.x < (unsigned)off) sh[threadIdx.x] += sh[threadIdx.x + off];
        __syncthreads();
    }
    if (threadIdx.x == 0) atomicAdd(&d_avg[0], sh[0]);
}

__global__ void scalers_kernel() {
    int i = blockIdx.x * blockDim.x + threadIdx.x;
    if (i < NN) {
        float avg  = d_avg[0] / (float)NN;
        float degc = fmaxf((float)d_deg[i], 1.f);
        float l    = logf(degc + 1.f);
        d_amp[i] = l / avg;
        d_att[i] = avg / l;
    }
}

// rbias / b2: out[c] = sum_j v[j]*W[j*ldw+c] + badd[c]   (one block, 128 threads)
__global__ void vecmat_kernel(const float* __restrict__ v, const float* __restrict__ W, int ldw,
                              const float* __restrict__ badd, float* __restrict__ out) {
    int c = threadIdx.x;
    float s = 0.f;
    for (int j = 0; j < HH; j++) s = fmaf(v[j], W[j * ldw + c], s);
    out[c] = s + badd[c];
}

// segmented aggregation: one block per node, 128 threads (one per column)
__global__ void agg_kernel() {
    int node = blockIdx.x;
    int c = threadIdx.x;
    int s = d_offs[node], e = d_offs[node + 1];
    float hd = d_pre[(size_t)node * 256 + c];
    float sum = 0.f, ss = 0.f, mn = INFINITY, mx = -INFINITY;
    for (int r = s; r < e; r++) {
        int sp = d_srcp[r];
        float v = d_mE[(size_t)r * HH + c] + hd + d_pre[(size_t)sp * 256 + 128 + c];
        sum += v;
        ss  = fmaf(v, v, ss);
        mn  = fminf(mn, v);
        mx  = fmaxf(mx, v);
    }
    float deg  = (float)(e - s);
    float degc = fmaxf(deg, 1.f);
    float mean = sum / degc;
    float var  = ss / degc - mean * mean;
    float sd   = sqrtf(fmaxf(var, 0.f) + 1e-5f);
    if (e == s) { mn = 0.f; mx = 0.f; }
    size_t o = (size_t)node * 512;
    d_agg[o +       c] = mean;
    d_agg[o + 128 + c] = mn;
    d_agg[o + 256 + c] = mx;
    d_agg[o + 384 + c] = sd;
}

// h_next = relu(z + y0 + amp*y1 + att*y2 + b2)
__global__ void combine_kernel(const float* __restrict__ b2, float* __restrict__ hout) {
    int i = blockIdx.x * blockDim.x + threadIdx.x;
    if (i >= NN * HH) return;
    int node = i >> 7, c = i & 127;
    size_t yo = (size_t)node * 384;
    float v = d_z[i] + d_y[yo + c] + d_amp[node] * d_y[yo + 128 + c]
            + d_att[node] * d_y[yo + 256 + c] + b2[c];
    hout[i] = fmaxf(v, 0.f);
}

__global__ void pool_kernel(const float* __restrict__ h, const int* __restrict__ batch) {
    int i = blockIdx.x * blockDim.x + threadIdx.x;
    if (i >= NN * HH) return;
    int node = i >> 7, c = i & 127;
    atomicAdd(&d_g[batch[node] * HH + c], h[i]);
}

__global__ void head_kernel(const float* __restrict__ W, const float* __restrict__ b,
                            float* __restrict__ out) {
    __shared__ float sh[HH];
    sh[threadIdx.x] = d_g[blockIdx.x * HH + threadIdx.x];
    __syncthreads();
    if (threadIdx.x < OUTC) {
        float s = b[threadIdx.x];
        for (int k = 0; k < HH; k++) s = fmaf(sh[k], W[k * OUTC + threadIdx.x], s);
        out[blockIdx.x * OUTC + threadIdx.x] = s;
    }
}

// ---------------- host orchestration ----------------
static void gemm(const float* A, int lda, const float* B, int ldb, float* C, int ldc,
                 int M, int N, int K, const float* bias, const int* perm) {
    dim3 grid(N / 128, (M + 127) / 128);
    sgemm_kernel<<<grid, 256>>>(A, lda, B, ldb, C, ldc, M, N, K, bias, perm);
}

template <typename T>
static T* sym(const void* symbol) {
    void* p = nullptr;
    cudaGetSymbolAddress(&p, symbol);
    return (T*)p;
}

extern "C" void kernel_launch(void* const* d_in, const int* in_sizes, int n_in,
                              void* d_out, int out_size) {
    const float* x        = (const float*)d_in[0];
    const float* eattr    = (const float*)d_in[1];
    const int*   src      = (const int*)  d_in[2];
    const int*   dst      = (const int*)  d_in[3];
    const int*   batch    = (const int*)  d_in[4];
    const float* nW       = (const float*)d_in[5];
    const float* nb       = (const float*)d_in[6];
    const float* eW       = (const float*)d_in[7];
    const float* eb       = (const float*)d_in[8];
    const float* encW     = (const float*)d_in[9];
    const float* encb     = (const float*)d_in[10];
    const float* preW     = (const float*)d_in[11];
    const float* preb     = (const float*)d_in[12];
    const float* postW    = (const float*)d_in[13];
    const float* postb    = (const float*)d_in[14];
    const float* linW     = (const float*)d_in[15];
    const float* linb     = (const float*)d_in[16];
    const float* headW    = (const float*)d_in[17];
    const float* headb    = (const float*)d_in[18];
    float* out = (float*)d_out;

    float* e0p  = sym<float>(d_e0p);
    float* mE   = sym<float>(d_mE);
    float* pre  = sym<float>(d_pre);
    float* agg  = sym<float>(d_agg);
    float* y    = sym<float>(d_y);
    float* z    = sym<float>(d_z);
    float* h0   = sym<float>(d_h0);
    float* h1   = sym<float>(d_h1);
    int*   deg  = sym<int>(d_deg);
    int*   offs = sym<int>(d_offs);
    int*   cnt  = sym<int>(d_cnt);
    int*   perm = sym<int>(d_perm);
    float* avg  = sym<float>(d_avg);
    float* R    = sym<float>(d_R);
    float* rb   = sym<float>(d_rb);
    float* Qcat = sym<float>(d_Qcat);
    float* Q0   = sym<float>(d_Q0);
    float* b2   = sym<float>(d_b2);
    float* g    = sym<float>(d_g);

    const int TPB = 256;

    // ---- graph structure (per launch; deterministic work) ----
    cudaMemsetAsync(deg, 0, NN * sizeof(int), 0);
    cudaMemsetAsync(avg, 0, sizeof(float), 0);
    count_kernel<<<(EE + TPB - 1) / TPB, TPB>>>(dst, EE);
    scan_kernel<<<1, 1024>>>();
    cudaMemcpyAsync(cnt, offs, NN * sizeof(int), cudaMemcpyDeviceToDevice, 0);
    scatter_kernel<<<(EE + TPB - 1) / TPB, TPB>>>(src, dst, EE);
    logdeg_sum_kernel<<<256, 256>>>();
    scalers_kernel<<<(NN + TPB - 1) / TPB, TPB>>>();

    // ---- embeddings ----
    // e0 permuted into CSR order directly (row gather on edge_attr)
    gemm(eattr, EIN, eW, HH, e0p, HH, EE, HH, EIN, eb, perm);
    // h = x @ node_emb_W + b
    gemm(x, FIN, nW, HH, h0, HH, NN, HH, FIN, nb, nullptr);

    // ---- per-layer weight precompute (independent of h) ----
    for (int l = 0; l < LL; l++) {
        const float* Wenc  = encW + (size_t)l * HH * HH;
        const float* Wpre2 = preW + (size_t)l * 3 * HH * HH + 2 * HH * HH;
        // R = Wenc @ Wpre2
        gemm(Wenc, HH, Wpre2, HH, R + (size_t)l * HH * HH, HH, HH, HH, HH, nullptr, nullptr);
        // rbias = benc @ Wpre2 + pre_b
        vecmat_kernel<<<1, HH>>>(encb + l * HH, Wpre2, HH, preb + l * HH, rb + l * HH);
        // Qcat = [P1|P2|P3] @ lin  ([512,384])
        const float* Pl  = postW + (size_t)l * 13 * HH * HH;
        const float* lin = linW + (size_t)l * HH * HH;
        for (int q = 0; q < 3; q++) {
            gemm(Pl + (size_t)(HH + q * 4 * HH) * HH, HH, lin, HH,
                 Qcat + (size_t)l * 4 * HH * 3 * HH + q * HH, 3 * HH,
                 4 * HH, HH, HH, nullptr, nullptr);
        }
        // Q0 = P0 @ lin
        gemm(Pl, HH, lin, HH, Q0 + (size_t)l * HH * HH, HH, HH, HH, HH, nullptr, nullptr);
        // b2 = post_b @ lin + lin_b
        vecmat_kernel<<<1, HH>>>(postb + l * HH, lin, HH, linb + l * HH, b2 + l * HH);
    }

    // ---- layers ----
    float* hcur = h0;
    float* hnext = h1;
    for (int l = 0; l < LL; l++) {
        const float* Wpre = preW + (size_t)l * 3 * HH * HH;
        // pre: hd = h@W0 -> cols [0,128), hs = h@W1 -> cols [128,256)
        gemm(hcur, HH, Wpre, HH, pre, 2 * HH, NN, HH, HH, nullptr, nullptr);
        gemm(hcur, HH, Wpre + (size_t)HH * HH, HH, pre + HH, 2 * HH, NN, HH, HH, nullptr, nullptr);
        // edge part: mE = e0p @ R_l + rbias_l   (CSR order)
        gemm(e0p, HH, R + (size_t)l * HH * HH, HH, mE, HH, EE, HH, HH, rb + l * HH, nullptr);
        // segmented aggregation -> agg [N,512]
        agg_kernel<<<NN, HH>>>();
        // y = agg @ Qcat_l  [N,384]
        gemm(agg, 4 * HH, Qcat + (size_t)l * 4 * HH * 3 * HH, 3 * HH, y, 3 * HH,
             NN, 3 * HH, 4 * HH, nullptr, nullptr);
        // z = h @ Q0_l
        gemm(hcur, HH, Q0 + (size_t)l * HH * HH, HH, z, HH, NN, HH, HH, nullptr, nullptr);
        // h_next = relu(z + y0 + amp*y1 + att*y2 + b2)
        combine_kernel<<<(NN * HH + TPB - 1) / TPB, TPB>>>(b2 + l * HH, hnext);
        float* t = hcur; hcur = hnext; hnext = t;
    }

    // ---- pool + head ----
    cudaMemsetAsync(g, 0, GG * HH * sizeof(float), 0);
    pool_kernel<<<(NN * HH + TPB - 1) / TPB, TPB>>>(hcur, batch);
    head_kernel<<<GG, HH>>>(headW, headb, out);
}

// round 2
// speedup vs baseline: 1.1149x; 1.1149x over previous
#include <cuda_runtime.h>
#include <math.h>
#include <cuda_bf16.h>

// ---------------- problem constants ----------------
static const int NN   = 50000;   // nodes
static const int EE   = 400000;  // edges
static const int FIN  = 64;
static const int EIN  = 16;
static const int HH   = 128;
static const int LL   = 4;
static const int GG   = 256;
static const int OUTC = 12;

// ---------------- scratch (static device globals; no runtime alloc) ----------------
__device__ float d_e0p[(size_t)EE * HH];        // permuted edge embedding (CSR order)
__device__ float d_mE [(size_t)EE * HH];        // per-edge message (edge part), CSR order
__device__ float d_pre[(size_t)NN * 2 * HH];    // [hd | hs]
__device__ float d_agg[(size_t)NN * 4 * HH];    // [mean|min|max|std]
__device__ float d_y  [(size_t)NN * 3 * HH];    // agg @ Qcat
__device__ float d_z  [(size_t)NN * HH];        // h @ Q0
__device__ float d_h0 [(size_t)NN * HH];
__device__ float d_h1 [(size_t)NN * HH];
__device__ int   d_deg [NN];
__device__ int   d_offs[NN + 1];
__device__ int   d_cnt [NN];
__device__ int   d_perm[EE];
__device__ int   d_srcp[EE];
__device__ float d_amp[NN];
__device__ float d_att[NN];
__device__ float d_avg[1];
__device__ float d_R   [LL * HH * HH];          // Wenc @ Wpre2
__device__ float d_rb  [LL * HH];               // benc@Wpre2 + pre_b
__device__ float d_Qcat[LL * 4 * HH * 3 * HH];  // [512,384] per layer: [P1|P2|P3]@lin
__device__ float d_Q0  [LL * HH * HH];          // P0@lin
__device__ float d_b2  [LL * HH];               // post_b@lin + lin_b
__device__ float d_g   [GG * HH];

// ---------------- packed f32x2 helpers ----------------
__device__ __forceinline__ unsigned long long dupf2(float a) {
    unsigned long long r;
    unsigned int ai = __float_as_uint(a);
    asm("mov.b64 %0, {%1, %1};" : "=l"(r) : "r"(ai));
    return r;
}
#define FMA2(d, a, b) asm("fma.rn.f32x2 %0, %1, %2, %0;" : "+l"(d) : "l"(a), "l"(b))

// ---------------- fp32 SGEMM with packed f32x2 FMA ----------------
// C[M,N] = A[M,K] @ B[K,N] (+bias), optional A-row gather via perm.
// BM=BN=128, BK=16, 256 threads, 8x8 per thread, double-buffered SMEM.
// Requires K%16==0, N%128==0, 16B-aligned pointers.
__global__ void __launch_bounds__(256, 2) sgemm_kernel(
    const float* __restrict__ A, int lda,
    const float* __restrict__ B, int ldb,
    float* __restrict__ C, int ldc,
    int M, int N, int K,
    const float* __restrict__ bias,
    const int* __restrict__ perm)
{
    const int BM = 128, BN = 128, BK = 16;
    __shared__ float As[2][BK][BM];
    __shared__ float Bs[2][BK][BN];

    int tid  = threadIdx.x;
    int brow = blockIdx.y, bcol = blockIdx.x;

    int aRow = tid >> 1;            // 0..127
    int aCol = (tid & 1) * 8;       // 0 or 8
    int bRow = tid >> 5;            // 0..7 (handles rows bRow and bRow+8)
    int bCol = (tid & 31) * 4;      // 0..124

    int tr = (tid >> 4) * 8;        // 0..120
    int tc = (tid & 15) * 8;        // 0..120

    unsigned long long acc[8][4];
#pragma unroll
    for (int i = 0; i < 8; i++)
#pragma unroll
        for (int j = 0; j < 4; j++) acc[i][j] = 0ull;

    int gArow = brow * BM + aRow;
    bool aValid = gArow < M;
    long arow_idx = 0;
    if (aValid) arow_idx = perm ? (long)perm[gArow] : (long)gArow;
    const float* Aptr = A + arow_idx * (long)lda + aCol;
    const float* Bptr = B + (long)bRow * ldb + (long)bcol * BN + bCol;

    const float4 f4z = make_float4(0.f, 0.f, 0.f, 0.f);
    const int ntiles = K >> 4;

    // prefetch tile 0 into smem buffer 0
    {
        float4 a0 = aValid ? *(const float4*)(Aptr)     : f4z;
        float4 a1 = aValid ? *(const float4*)(Aptr + 4) : f4z;
        float4 b0 = *(const float4*)(Bptr);
        float4 b1 = *(const float4*)(Bptr + 8L * ldb);
        As[0][aCol + 0][aRow] = a0.x; As[0][aCol + 1][aRow] = a0.y;
        As[0][aCol + 2][aRow] = a0.z; As[0][aCol + 3][aRow] = a0.w;
        As[0][aCol + 4][aRow] = a1.x; As[0][aCol + 5][aRow] = a1.y;
        As[0][aCol + 6][aRow] = a1.z; As[0][aCol + 7][aRow] = a1.w;
        *(float4*)&Bs[0][bRow][bCol]     = b0;
        *(float4*)&Bs[0][bRow + 8][bCol] = b1;
    }
    __syncthreads();

    int buf = 0;
    for (int t = 0; t < ntiles; t++) {
        bool more = (t + 1 < ntiles);
        float4 na0, na1, nb0, nb1;
        if (more) {
            int k0 = (t + 1) << 4;
            na0 = aValid ? *(const float4*)(Aptr + k0)     : f4z;
            na1 = aValid ? *(const float4*)(Aptr + k0 + 4) : f4z;
            nb0 = *(const float4*)(Bptr + (long)k0 * ldb);
            nb1 = *(const float4*)(Bptr + (long)(k0 + 8) * ldb);
        }
#pragma unroll
        for (int kk = 0; kk < BK; kk++) {
            const float* As_k = &As[buf][kk][tr];
            float4 av0 = *(const float4*)As_k;
            float4 av1 = *(const float4*)(As_k + 4);
            const unsigned long long* Bp =
                (const unsigned long long*)&Bs[buf][kk][tc];
            unsigned long long bv0 = Bp[0], bv1 = Bp[1], bv2 = Bp[2], bv3 = Bp[3];
            float ar[8] = {av0.x, av0.y, av0.z, av0.w, av1.x, av1.y, av1.z, av1.w};
#pragma unroll
            for (int i = 0; i < 8; i++) {
                unsigned long long ad = dupf2(ar[i]);
                FMA2(acc[i][0], ad, bv0);
                FMA2(acc[i][1], ad, bv1);
                FMA2(acc[i][2], ad, bv2);
                FMA2(acc[i][3], ad, bv3);
            }
        }
        if (more) {
            int nb = buf ^ 1;
            As[nb][aCol + 0][aRow] = na0.x; As[nb][aCol + 1][aRow] = na0.y;
            As[nb][aCol + 2][aRow] = na0.z; As[nb][aCol + 3][aRow] = na0.w;
            As[nb][aCol + 4][aRow] = na1.x; As[nb][aCol + 5][aRow] = na1.y;
            As[nb][aCol + 6][aRow] = na1.z; As[nb][aCol + 7][aRow] = na1.w;
            *(float4*)&Bs[nb][bRow][bCol]     = nb0;
            *(float4*)&Bs[nb][bRow + 8][bCol] = nb1;
            __syncthreads();
            buf = nb;
        }
    }

#pragma unroll
    for (int i = 0; i < 8; i++) {
        int row = brow * BM + tr + i;
        if (row < M) {
#pragma unroll
            for (int j = 0; j < 4; j += 2) {
                int col = bcol * BN + tc + j * 2;
                float2 p0 = *(float2*)&acc[i][j];
                float2 p1 = *(float2*)&acc[i][j + 1];
                float4 v;
                v.x = p0.x + (bias ? bias[col + 0] : 0.f);
                v.y = p0.y + (bias ? bias[col + 1] : 0.f);
                v.z = p1.x + (bias ? bias[col + 2] : 0.f);
                v.w = p1.y + (bias ? bias[col + 3] : 0.f);
                *(float4*)&C[(long)row * ldc + col] = v;
            }
        }
    }
}

// ---------------- small helper kernels ----------------
__global__ void count_kernel(const int* __restrict__ dst, int n) {
    int i = blockIdx.x * blockDim.x + threadIdx.x;
    if (i < n) atomicAdd(&d_deg[dst[i]], 1);
}

// single-block exclusive scan of d_deg[0..NN) -> d_offs[0..NN]
__global__ void scan_kernel() {
    __shared__ int sh[1024];
    __shared__ int carry;
    if (threadIdx.x == 0) carry = 0;
    __syncthreads();
    for (int base = 0; base < NN; base += 1024) {
        int i = base + (int)threadIdx.x;
        int v = (i < NN) ? d_deg[i] : 0;
        sh[threadIdx.x] = v;
        __syncthreads();
        for (int off = 1; off < 1024; off <<= 1) {
            int t = (threadIdx.x >= (unsigned)off) ? sh[threadIdx.x - off] : 0;
            __syncthreads();
            sh[threadIdx.x] += t;
            __syncthreads();
        }
        if (i < NN) d_offs[i] = carry + sh[threadIdx.x] - v;
        __syncthreads();
        if (threadIdx.x == 1023) carry += sh[1023];
        __syncthreads();
    }
    if (threadIdx.x == 0) d_offs[NN] = carry;
}

__global__ void scatter_kernel(const int* __restrict__ src, const int* __restrict__ dst, int n) {
    int i = blockIdx.x * blockDim.x + threadIdx.x;
    if (i < n) {
        int pos = atomicAdd(&d_cnt[dst[i]], 1);
        d_perm[pos] = i;
        d_srcp[pos] = src[i];
    }
}

__global__ void logdeg_sum_kernel() {
    __shared__ float sh[256];
    float s = 0.f;
    for (int i = blockIdx.x * blockDim.x + threadIdx.x; i < NN; i += gridDim.x * blockDim.x)
        s += log1pf((float)d_deg[i]);
    sh[threadIdx.x] = s;
    __syncthreads();
    for (int off = 128; off > 0; off >>= 1) {
        if (threadIdx.x < (unsigned)off) sh[threadIdx.x] += sh[threadIdx.x + off];
        __syncthreads();
    }
    if (threadIdx.x == 0) atomicAdd(&d_avg[0], sh[0]);
}

__global__ void scalers_kernel() {
    int i = blockIdx.x * blockDim.x + threadIdx.x;
    if (i < NN) {
        float avg  = d_avg[0] / (float)NN;
        float degc = fmaxf((float)d_deg[i], 1.f);
        float l    = logf(degc + 1.f);
        d_amp[i] = l / avg;
        d_att[i] = avg / l;
    }
}

// rbias / b2: out[c] = sum_j v[j]*W[j*ldw+c] + badd[c]   (one block, 128 threads)
__global__ void vecmat_kernel(const float* __restrict__ v, const float* __restrict__ W, int ldw,
                              const float* __restrict__ badd, float* __restrict__ out) {
    int c = threadIdx.x;
    float s = 0.f;
    for (int j = 0; j < HH; j++) s = fmaf(v[j], W[j * ldw + c], s);
    out[c] = s + badd[c];
}

// segmented aggregation: one block per node, 128 threads (one per column)
__global__ void agg_kernel() {
    int node = blockIdx.x;
    int c = threadIdx.x;
    int s = d_offs[node], e = d_offs[node + 1];
    float hd = d_pre[(size_t)node * 256 + c];
    float sum = 0.f, ss = 0.f, mn = INFINITY, mx = -INFINITY;
    for (int r = s; r < e; r++) {
        int sp = d_srcp[r];
        float v = d_mE[(size_t)r * HH + c] + hd + d_pre[(size_t)sp * 256 + 128 + c];
        sum += v;
        ss  = fmaf(v, v, ss);
        mn  = fminf(mn, v);
        mx  = fmaxf(mx, v);
    }
    float deg  = (float)(e - s);
    float degc = fmaxf(deg, 1.f);
    float mean = sum / degc;
    float var  = ss / degc - mean * mean;
    float sd   = sqrtf(fmaxf(var, 0.f) + 1e-5f);
    if (e == s) { mn = 0.f; mx = 0.f; }
    size_t o = (size_t)node * 512;
    d_agg[o +       c] = mean;
    d_agg[o + 128 + c] = mn;
    d_agg[o + 256 + c] = mx;
    d_agg[o + 384 + c] = sd;
}

// h_next = relu(z + y0 + amp*y1 + att*y2 + b2)
__global__ void combine_kernel(const float* __restrict__ b2, float* __restrict__ hout) {
    int i = blockIdx.x * blockDim.x + threadIdx.x;
    if (i >= NN * HH) return;
    int node = i >> 7, c = i & 127;
    size_t yo = (size_t)node * 384;
    float v = d_z[i] + d_y[yo + c] + d_amp[node] * d_y[yo + 128 + c]
            + d_att[node] * d_y[yo + 256 + c] + b2[c];
    hout[i] = fmaxf(v, 0.f);
}

__global__ void pool_kernel(const float* __restrict__ h, const int* __restrict__ batch) {
    int i = blockIdx.x * blockDim.x + threadIdx.x;
    if (i >= NN * HH) return;
    int node = i >> 7, c = i & 127;
    atomicAdd(&d_g[batch[node] * HH + c], h[i]);
}

__global__ void head_kernel(const float* __restrict__ W, const float* __restrict__ b,
                            float* __restrict__ out) {
    __shared__ float sh[HH];
    sh[threadIdx.x] = d_g[blockIdx.x * HH + threadIdx.x];
    __syncthreads();
    if (threadIdx.x < OUTC) {
        float s = b[threadIdx.x];
        for (int k = 0; k < HH; k++) s = fmaf(sh[k], W[k * OUTC + threadIdx.x], s);
        out[blockIdx.x * OUTC + threadIdx.x] = s;
    }
}

// ---------------- host orchestration ----------------
static void gemm(const float* A, int lda, const float* B, int ldb, float* C, int ldc,
                 int M, int N, int K, const float* bias, const int* perm) {
    dim3 grid(N / 128, (M + 127) / 128);
    sgemm_kernel<<<grid, 256>>>(A, lda, B, ldb, C, ldc, M, N, K, bias, perm);
}

template <typename T>
static T* sym(const void* symbol) {
    void* p = nullptr;
    cudaGetSymbolAddress(&p, symbol);
    return (T*)p;
}

extern "C" void kernel_launch(void* const* d_in, const int* in_sizes, int n_in,
                              void* d_out, int out_size) {
    const float* x        = (const float*)d_in[0];
    const float* eattr    = (const float*)d_in[1];
    const int*   src      = (const int*)  d_in[2];
    const int*   dst      = (const int*)  d_in[3];
    const int*   batch    = (const int*)  d_in[4];
    const float* nW       = (const float*)d_in[5];
    const float* nb       = (const float*)d_in[6];
    const float* eW       = (const float*)d_in[7];
    const float* eb       = (const float*)d_in[8];
    const float* encW     = (const float*)d_in[9];
    const float* encb     = (const float*)d_in[10];
    const float* preW     = (const float*)d_in[11];
    const float* preb     = (const float*)d_in[12];
    const float* postW    = (const float*)d_in[13];
    const float* postb    = (const float*)d_in[14];
    const float* linW     = (const float*)d_in[15];
    const float* linb     = (const float*)d_in[16];
    const float* headW    = (const float*)d_in[17];
    const float* headb    = (const float*)d_in[18];
    float* out = (float*)d_out;

    float* e0p  = sym<float>(d_e0p);
    float* mE   = sym<float>(d_mE);
    float* pre  = sym<float>(d_pre);
    float* agg  = sym<float>(d_agg);
    float* y    = sym<float>(d_y);
    float* z    = sym<float>(d_z);
    float* h0   = sym<float>(d_h0);
    float* h1   = sym<float>(d_h1);
    int*   deg  = sym<int>(d_deg);
    int*   offs = sym<int>(d_offs);
    int*   cnt  = sym<int>(d_cnt);
    int*   perm = sym<int>(d_perm);
    float* avg  = sym<float>(d_avg);
    float* R    = sym<float>(d_R);
    float* rb   = sym<float>(d_rb);
    float* Qcat = sym<float>(d_Qcat);
    float* Q0   = sym<float>(d_Q0);
    float* b2   = sym<float>(d_b2);
    float* g    = sym<float>(d_g);

    const int TPB = 256;

    // ---- graph structure (per launch; deterministic work) ----
    cudaMemsetAsync(deg, 0, NN * sizeof(int), 0);
    cudaMemsetAsync(avg, 0, sizeof(float), 0);
    count_kernel<<<(EE + TPB - 1) / TPB, TPB>>>(dst, EE);
    scan_kernel<<<1, 1024>>>();
    cudaMemcpyAsync(cnt, offs, NN * sizeof(int), cudaMemcpyDeviceToDevice, 0);
    scatter_kernel<<<(EE + TPB - 1) / TPB, TPB>>>(src, dst, EE);
    logdeg_sum_kernel<<<256, 256>>>();
    scalers_kernel<<<(NN + TPB - 1) / TPB, TPB>>>();

    // ---- embeddings ----
    // e0 permuted into CSR order directly (row gather on edge_attr)
    gemm(eattr, EIN, eW, HH, e0p, HH, EE, HH, EIN, eb, perm);
    // h = x @ node_emb_W + b
    gemm(x, FIN, nW, HH, h0, HH, NN, HH, FIN, nb, nullptr);

    // ---- per-layer weight precompute (independent of h) ----
    for (int l = 0; l < LL; l++) {
        const float* Wenc  = encW + (size_t)l * HH * HH;
        const float* Wpre2 = preW + (size_t)l * 3 * HH * HH + 2 * HH * HH;
        // R = Wenc @ Wpre2
        gemm(Wenc, HH, Wpre2, HH, R + (size_t)l * HH * HH, HH, HH, HH, HH, nullptr, nullptr);
        // rbias = benc @ Wpre2 + pre_b
        vecmat_kernel<<<1, HH>>>(encb + l * HH, Wpre2, HH, preb + l * HH, rb + l * HH);
        // Qcat = [P1|P2|P3] @ lin  ([512,384])
        const float* Pl  = postW + (size_t)l * 13 * HH * HH;
        const float* lin = linW + (size_t)l * HH * HH;
        for (int q = 0; q < 3; q++) {
            gemm(Pl + (size_t)(HH + q * 4 * HH) * HH, HH, lin, HH,
                 Qcat + (size_t)l * 4 * HH * 3 * HH + q * HH, 3 * HH,
                 4 * HH, HH, HH, nullptr, nullptr);
        }
        // Q0 = P0 @ lin
        gemm(Pl, HH, lin, HH, Q0 + (size_t)l * HH * HH, HH, HH, HH, HH, nullptr, nullptr);
        // b2 = post_b @ lin + lin_b
        vecmat_kernel<<<1, HH>>>(postb + l * HH, lin, HH, linb + l * HH, b2 + l * HH);
    }

    // ---- layers ----
    float* hcur = h0;
    float* hnext = h1;
    for (int l = 0; l < LL; l++) {
        const float* Wpre = preW + (size_t)l * 3 * HH * HH;
        // pre: hd = h@W0 -> cols [0,128), hs = h@W1 -> cols [128,256)
        gemm(hcur, HH, Wpre, HH, pre, 2 * HH, NN, HH, HH, nullptr, nullptr);
        gemm(hcur, HH, Wpre + (size_t)HH * HH, HH, pre + HH, 2 * HH, NN, HH, HH, nullptr, nullptr);
        // edge part: mE = e0p @ R_l + rbias_l   (CSR order)
        gemm(e0p, HH, R + (size_t)l * HH * HH, HH, mE, HH, EE, HH, HH, rb + l * HH, nullptr);
        // segmented aggregation -> agg [N,512]
        agg_kernel<<<NN, HH>>>();
        // y = agg @ Qcat_l  [N,384]
        gemm(agg, 4 * HH, Qcat + (size_t)l * 4 * HH * 3 * HH, 3 * HH, y, 3 * HH,
             NN, 3 * HH, 4 * HH, nullptr, nullptr);
        // z = h @ Q0_l
        gemm(hcur, HH, Q0 + (size_t)l * HH * HH, HH, z, HH, NN, HH, HH, nullptr, nullptr);
        // h_next = relu(z + y0 + amp*y1 + att*y2 + b2)
        combine_kernel<<<(NN * HH + TPB - 1) / TPB, TPB>>>(b2 + l * HH, hnext);
        float* t = hcur; hcur = hnext; hnext = t;
    }

    // ---- pool + head ----
    cudaMemsetAsync(g, 0, GG * HH * sizeof(float), 0);
    pool_kernel<<<(NN * HH + TPB - 1) / TPB, TPB>>>(hcur, batch);
    head_kernel<<<GG, HH>>>(headW, headb, out);
}

// round 4
// speedup vs baseline: 1.6742x; 1.5016x over previous
#include <cuda_runtime.h>
#include <math.h>
#include <stdint.h>
#include <cuda_bf16.h>

// ---------------- problem constants ----------------
static const int NN   = 50000;   // nodes
static const int EE   = 400000;  // edges
static const int FIN  = 64;
static const int EIN  = 16;
static const int HH   = 128;
static const int LL   = 4;
static const int GG   = 256;
static const int OUTC = 12;

// ---------------- scratch (static device globals; no runtime alloc) ----------------
__device__ float d_e0p[(size_t)EE * HH];        // permuted edge embedding (CSR order), fp32
__device__ __nv_bfloat16 d_e0h[(size_t)EE * HH];
__device__ __nv_bfloat16 d_e0l[(size_t)EE * HH];
__device__ float d_mE [(size_t)EE * HH];        // per-edge message (edge part), CSR order
__device__ float d_cmb[(size_t)NN * 3 * HH];    // [hd | hs | z] per node
__device__ __nv_bfloat16 d_agh[(size_t)NN * 4 * HH];
__device__ __nv_bfloat16 d_agl[(size_t)NN * 4 * HH];
__device__ float d_y  [(size_t)NN * 3 * HH];    // agg @ Qcat
__device__ float d_h0 [(size_t)NN * HH];
__device__ float d_h1 [(size_t)NN * HH];
__device__ __nv_bfloat16 d_hh0[(size_t)NN * HH];
__device__ __nv_bfloat16 d_hl0[(size_t)NN * HH];
__device__ __nv_bfloat16 d_hh1[(size_t)NN * HH];
__device__ __nv_bfloat16 d_hl1[(size_t)NN * HH];
__device__ int   d_deg [NN];
__device__ int   d_offs[NN + 1];
__device__ int   d_cnt [NN];
__device__ int   d_perm[EE];
__device__ int   d_srcp[EE];
__device__ float d_amp[NN];
__device__ float d_att[NN];
__device__ float d_avg[1];
__device__ float d_R   [LL * HH * HH];          // Wenc @ Wpre2
__device__ float d_rb  [LL * HH];               // benc@Wpre2 + pre_b
__device__ float d_Qcat[LL * 4 * HH * 3 * HH];  // [512,384] per layer
__device__ float d_Q0  [LL * HH * HH];          // P0@lin
__device__ float d_b2  [LL * HH];               // post_b@lin + lin_b
__device__ float d_g   [GG * HH];
// transposed bf16-split weights (Bt layout: [N,K] row-major)
__device__ __nv_bfloat16 d_Wch[LL * 3 * HH * HH], d_Wcl[LL * 3 * HH * HH];   // [384,128]: W0|W1|Q0
__device__ __nv_bfloat16 d_Rth[LL * HH * HH],     d_Rtl[LL * HH * HH];       // [128,128]
__device__ __nv_bfloat16 d_Qch[LL * 3 * HH * 4 * HH], d_Qcl[LL * 3 * HH * 4 * HH]; // [384,512]

// ================= warp-level bf16 MMA GEMM (mma.sync, sm_80+ portable) =================
// C[M, gridDim.y*128] = A @ Bt^T (+bias). A: bf16 hi/lo [M,K] row-major.
// Bt: bf16 hi/lo [N,K] row-major. bf16x3: D = Ah*Bh + Ah*Bl + Al*Bh. K % 32 == 0.
// Block 256 thr = 8 warps (4x2), warp tile 32x64, BK=32, cp.async double buffer.
static const int HPAD = 40;                 // padded K-stride in bf16 (conflict-free ldmatrix)
static const int TILEB = 128 * HPAD * 2;    // 10240 B per tile
static const int BUFB  = 4 * TILEB;         // Ah,Al,Bh,Bl
static const int TSMEM = 2 * BUFB;          // 81920 B

#define LDSM4(R, ADDR) \
    asm volatile("ldmatrix.sync.aligned.m8n8.x4.shared.b16 {%0,%1,%2,%3}, [%4];" \
        : "=r"((R)[0]), "=r"((R)[1]), "=r"((R)[2]), "=r"((R)[3]) : "r"(ADDR))

#define MMA16816(D, A, B) \
    asm volatile("mma.sync.aligned.m16n8k16.row.col.f32.bf16.bf16.f32 " \
        "{%0,%1,%2,%3}, {%4,%5,%6,%7}, {%8,%9}, {%0,%1,%2,%3};" \
        : "+f"((D)[0]), "+f"((D)[1]), "+f"((D)[2]), "+f"((D)[3]) \
        : "r"((A)[0]), "r"((A)[1]), "r"((A)[2]), "r"((A)[3]), "r"((B)[0]), "r"((B)[1]))

__device__ __forceinline__ uint32_t smem_u32(const void* p) {
    uint32_t a;
    asm("{ .reg .u64 t; cvta.to.shared.u64 t, %1; cvt.u32.u64 %0, t; }" : "=r"(a) : "l"(p));
    return a;
}

__global__ void __launch_bounds__(256) hmma_kernel(
    const __nv_bfloat16* __restrict__ Ah, const __nv_bfloat16* __restrict__ Al,
    const __nv_bfloat16* __restrict__ Bh, const __nv_bfloat16* __restrict__ Bl,
    float* __restrict__ C, int ldc, int M, int K,
    const float* __restrict__ bias)
{
    extern __shared__ char smem[];
    const uint32_t sb = smem_u32(smem);
    const int tid = threadIdx.x, lane = tid & 31, wid = tid >> 5;
    const int warp_m = wid & 3, warp_n = wid >> 2;         // 4 x 2 warps
    const int m0 = blockIdx.x * 128, n0 = blockIdx.y * 128;

    const int OAH = 0, OAL = TILEB, OBH = 2 * TILEB, OBL = 3 * TILEB;

    float acc[2][8][4];
#pragma unroll
    for (int i = 0; i < 2; i++)
#pragma unroll
        for (int j = 0; j < 8; j++)
#pragma unroll
            for (int k = 0; k < 4; k++) acc[i][j][k] = 0.f;

    // ---- cp.async tile loader: 128 rows x 32 bf16, 256 threads x2 iters of 16B ----
    const int ldr = tid >> 2;            // 0..63
    const int ldc8 = (tid & 3) * 8;      // bf16 col: 0,8,16,24
    auto issue_chunk = [&](int buf, int k0) {
        uint32_t bo = sb + buf * BUFB;
#pragma unroll
        for (int half = 0; half < 2; half++) {
            int r = half * 64 + ldr;
            uint32_t soff = (uint32_t)(r * HPAD + ldc8) * 2;
            // A hi/lo (row-guarded, zero-fill OOB)
            int arow = m0 + r;
            int asz = (arow < M) ? 16 : 0;
            const void* gah = Ah + (size_t)arow * K + k0 + ldc8;
            const void* gal = Al + (size_t)arow * K + k0 + ldc8;
            asm volatile("cp.async.cg.shared.global [%0], [%1], 16, %2;"
                         :: "r"(bo + OAH + soff), "l"(gah), "r"(asz));
            asm volatile("cp.async.cg.shared.global [%0], [%1], 16, %2;"
                         :: "r"(bo + OAL + soff), "l"(gal), "r"(asz));
            // B hi/lo (always valid)
            const void* gbh = Bh + (size_t)(n0 + r) * K + k0 + ldc8;
            const void* gbl = Bl + (size_t)(n0 + r) * K + k0 + ldc8;
            asm volatile("cp.async.cg.shared.global [%0], [%1], 16;"
                         :: "r"(bo + OBH + soff), "l"(gbh));
            asm volatile("cp.async.cg.shared.global [%0], [%1], 16;"
                         :: "r"(bo + OBL + soff), "l"(gbl));
        }
        asm volatile("cp.async.commit_group;");
    };

    // ldmatrix lane addressing
    const int a_r  = lane & 15;          // row within 16
    const int a_kg = (lane >> 4) * 8;    // k-offset 0/8
    const int b_r  = (lane & 7) + ((lane >> 4) * 8);  // n row within 16 (g>>1)*8
    const int b_kg = ((lane >> 3) & 1) * 8;           // k-offset (g&1)*8

    const int nchunks = K >> 5;
    issue_chunk(0, 0);

    for (int ch = 0; ch < nchunks; ch++) {
        asm volatile("cp.async.wait_group 0;");
        __syncthreads();
        if (ch + 1 < nchunks) issue_chunk((ch + 1) & 1, (ch + 1) << 5);

        uint32_t bo = sb + (ch & 1) * BUFB;
#pragma unroll
        for (int ks = 0; ks < 2; ks++) {
            int kc = ks * 16;
            uint32_t afh[2][4], afl[2][4], bfh[4][4], bfl[4][4];
#pragma unroll
            for (int mt = 0; mt < 2; mt++) {
                int row = warp_m * 32 + mt * 16 + a_r;
                uint32_t ad = bo + (uint32_t)(row * HPAD + kc + a_kg) * 2;
                LDSM4(afh[mt], ad + OAH);
                LDSM4(afl[mt], ad + OAL);
            }
#pragma unroll
            for (int np = 0; np < 4; np++) {
                int nrow = warp_n * 64 + np * 16 + b_r;
                uint32_t bd = bo + (uint32_t)(nrow * HPAD + kc + b_kg) * 2;
                LDSM4(bfh[np], bd + OBH);
                LDSM4(bfl[np], bd + OBL);
            }
#pragma unroll
            for (int mt = 0; mt < 2; mt++)
#pragma unroll
                for (int np = 0; np < 4; np++) {
                    MMA16816(acc[mt][np * 2 + 0], afh[mt], (&bfh[np][0]));
                    MMA16816(acc[mt][np * 2 + 1], afh[mt], (&bfh[np][2]));
                    MMA16816(acc[mt][np * 2 + 0], afl[mt], (&bfh[np][0]));
                    MMA16816(acc[mt][np * 2 + 1], afl[mt], (&bfh[np][2]));
                    MMA16816(acc[mt][np * 2 + 0], afh[mt], (&bfl[np][0]));
                    MMA16816(acc[mt][np * 2 + 1], afh[mt], (&bfl[np][2]));
                }
        }
    }

    // ---- epilogue ----
    const int mrow = m0 + warp_m * 32;
    const int ncol = n0 + warp_n * 64;
#pragma unroll
    for (int mt = 0; mt < 2; mt++) {
#pragma unroll
        for (int nt = 0; nt < 8; nt++) {
            int c = ncol + nt * 8 + (lane & 3) * 2;
            float2 bv = bias ? *(const float2*)&bias[c] : make_float2(0.f, 0.f);
            int r0 = mrow + mt * 16 + (lane >> 2);
            if (r0 < M) {
                float2 v = make_float2(acc[mt][nt][0] + bv.x, acc[mt][nt][1] + bv.y);
                *(float2*)&C[(size_t)r0 * ldc + c] = v;
            }
            int r1 = r0 + 8;
            if (r1 < M) {
                float2 v = make_float2(acc[mt][nt][2] + bv.x, acc[mt][nt][3] + bv.y);
                *(float2*)&C[(size_t)r1 * ldc + c] = v;
            }
        }
    }
}

// ---------------- split / transpose-convert helpers ----------------
__device__ __forceinline__ void split1(float x, __nv_bfloat16& h, __nv_bfloat16& l) {
    h = __float2bfloat16(x);
    l = __float2bfloat16(x - __bfloat162float(h));
}

__global__ void split_kernel(const float* __restrict__ in,
                             __nv_bfloat16* __restrict__ hi,
                             __nv_bfloat16* __restrict__ lo, long n) {
    long i = (long)blockIdx.x * blockDim.x + threadIdx.x;
    if (i < n) { __nv_bfloat16 h, l; split1(in[i], h, l); hi[i] = h; lo[i] = l; }
}

// in [K,N] fp32 row-major -> out hi/lo [N,K] bf16 row-major
__global__ void tconv_kernel(const float* __restrict__ in,
                             __nv_bfloat16* __restrict__ hi,
                             __nv_bfloat16* __restrict__ lo, int K, int N) {
    int i = blockIdx.x * blockDim.x + threadIdx.x;
    if (i < K * N) {
        int n = i / K, k = i - n * K;
        __nv_bfloat16 h, l; split1(in[(size_t)k * N + n], h, l);
        hi[(size_t)n * K + k] = h; lo[(size_t)n * K + k] = l;
    }
}

// ---------------- fp32 SGEMM (small GEMMs + gathered edge embedding) ----------------
__global__ void __launch_bounds__(256) sgemm_kernel(
    const float* __restrict__ A, int lda,
    const float* __restrict__ B, int ldb,
    float* __restrict__ C, int ldc,
    int M, int N, int K,
    const float* __restrict__ bias,
    const int* __restrict__ perm)
{
    const int BM = 128, BN = 128, BK = 8;
    __shared__ float As[BK][BM];
    __shared__ float Bs[BK][BN];
    int tid = threadIdx.x;
    int brow = blockIdx.y, bcol = blockIdx.x;
    int aRow = tid >> 1, aCol4 = (tid & 1) * 4;
    int bRow = tid >> 5, bCol4 = (tid & 31) * 4;
    int tr = (tid >> 4) * 8, tc = (tid & 15) * 8;
    float acc[8][8];
#pragma unroll
    for (int i = 0; i < 8; i++)
#pragma unroll
        for (int j = 0; j < 8; j++) acc[i][j] = 0.f;
    int gArow = brow * BM + aRow;
    bool aValid = gArow < M;
    long arow_idx = 0;
    if (aValid) arow_idx = perm ? (long)perm[gArow] : (long)gArow;
    const float* Aptr = A + arow_idx * (long)lda + aCol4;
    const float* Bptr = B + (long)bRow * ldb + (long)bcol * BN + bCol4;
    for (int k0 = 0; k0 < K; k0 += BK) {
        float4 av = aValid ? *(const float4*)(Aptr + k0) : make_float4(0.f, 0.f, 0.f, 0.f);
        float4 bv = *(const float4*)(Bptr + (long)k0 * ldb);
        As[aCol4 + 0][aRow] = av.x; As[aCol4 + 1][aRow] = av.y;
        As[aCol4 + 2][aRow] = av.z; As[aCol4 + 3][aRow] = av.w;
        *(float4*)&Bs[bRow][bCol4] = bv;
        __syncthreads();
#pragma unroll
        for (int kk = 0; kk < BK; kk++) {
            float ar[8], br[8];
#pragma unroll
            for (int i = 0; i < 8; i++) ar[i] = As[kk][tr + i];
#pragma unroll
            for (int j = 0; j < 8; j++) br[j] = Bs[kk][tc + j];
#pragma unroll
            for (int i = 0; i < 8; i++)
#pragma unroll
                for (int j = 0; j < 8; j++)
                    acc[i][j] = fmaf(ar[i], br[j], acc[i][j]);
        }
        __syncthreads();
    }
#pragma unroll
    for (int i = 0; i < 8; i++) {
        int row = brow * BM + tr + i;
        if (row < M) {
#pragma unroll
            for (int j = 0; j < 8; j += 4) {
                int col = bcol * BN + tc + j;
                float4 v;
                v.x = acc[i][j + 0] + (bias ? bias[col + 0] : 0.f);
                v.y = acc[i][j + 1] + (bias ? bias[col + 1] : 0.f);
                v.z = acc[i][j + 2] + (bias ? bias[col + 2] : 0.f);
                v.w = acc[i][j + 3] + (bias ? bias[col + 3] : 0.f);
                *(float4*)&C[(long)row * ldc + col] = v;
            }
        }
    }
}

// ---------------- small helper kernels ----------------
__global__ void count_kernel(const int* __restrict__ dst, int n) {
    int i = blockIdx.x * blockDim.x + threadIdx.x;
    if (i < n) atomicAdd(&d_deg[dst[i]], 1);
}

__global__ void scan_kernel() {
    __shared__ int sh[1024];
    __shared__ int carry;
    if (threadIdx.x == 0) carry = 0;
    __syncthreads();
    for (int base = 0; base < NN; base += 1024) {
        int i = base + (int)threadIdx.x;
        int v = (i < NN) ? d_deg[i] : 0;
        sh[threadIdx.x] = v;
        __syncthreads();
        for (int off = 1; off < 1024; off <<= 1) {
            int t = (threadIdx.x >= (unsigned)off) ? sh[threadIdx.x - off] : 0;
            __syncthreads();
            sh[threadIdx.x] += t;
            __syncthreads();
        }
        if (i < NN) d_offs[i] = carry + sh[threadIdx.x] - v;
        __syncthreads();
        if (threadIdx.x == 1023) carry += sh[1023];
        __syncthreads();
    }
    if (threadIdx.x == 0) d_offs[NN] = carry;
}

__global__ void scatter_kernel(const int* __restrict__ src, const int* __restrict__ dst, int n) {
    int i = blockIdx.x * blockDim.x + threadIdx.x;
    if (i < n) {
        int pos = atomicAdd(&d_cnt[dst[i]], 1);
        d_perm[pos] = i;
        d_srcp[pos] = src[i];
    }
}

__global__ void logdeg_sum_kernel() {
    __shared__ float sh[256];
    float s = 0.f;
    for (int i = blockIdx.x * blockDim.x + threadIdx.x; i < NN; i += gridDim.x * blockDim.x)
        s += log1pf((float)d_deg[i]);
    sh[threadIdx.x] = s;
    __syncthreads();
    for (int off = 128; off > 0; off >>= 1) {
        if (threadIdx.x < (unsigned)off) sh[threadIdx.x] += sh[threadIdx.x + off];
        __syncthreads();
    }
    if (threadIdx.x == 0) atomicAdd(&d_avg[0], sh[0]);
}

__global__ void scalers_kernel() {
    int i = blockIdx.x * blockDim.x + threadIdx.x;
    if (i < NN) {
        float avg  = d_avg[0] / (float)NN;
        float degc = fmaxf((float)d_deg[i], 1.f);
        float l    = logf(degc + 1.f);
        d_amp[i] = l / avg;
        d_att[i] = avg / l;
    }
}

__global__ void vecmat_kernel(const float* __restrict__ v, const float* __restrict__ W, int ldw,
                              const float* __restrict__ badd, float* __restrict__ out) {
    int c = threadIdx.x;
    float s = 0.f;
    for (int j = 0; j < HH; j++) s = fmaf(v[j], W[j * ldw + c], s);
    out[c] = s + badd[c];
}

// segmented aggregation -> bf16-split agg [N,512]; cmb layout [hd|hs|z] stride 384
__global__ void agg_kernel() {
    int node = blockIdx.x;
    int c = threadIdx.x;
    int s = d_offs[node], e = d_offs[node + 1];
    float hd = d_cmb[(size_t)node * 384 + c];
    float sum = 0.f, ss = 0.f, mn = INFINITY, mx = -INFINITY;
    for (int r = s; r < e; r++) {
        int sp = d_srcp[r];
        float v = d_mE[(size_t)r * HH + c] + hd + d_cmb[(size_t)sp * 384 + 128 + c];
        sum += v;
        ss  = fmaf(v, v, ss);
        mn  = fminf(mn, v);
        mx  = fmaxf(mx, v);
    }
    float deg  = (float)(e - s);
    float degc = fmaxf(deg, 1.f);
    float mean = sum / degc;
    float var  = ss / degc - mean * mean;
    float sd   = sqrtf(fmaxf(var, 0.f) + 1e-5f);
    if (e == s) { mn = 0.f; mx = 0.f; }
    size_t o = (size_t)node * 512;
    __nv_bfloat16 h, l;
    split1(mean, h, l); d_agh[o +       c] = h; d_agl[o +       c] = l;
    split1(mn,   h, l); d_agh[o + 128 + c] = h; d_agl[o + 128 + c] = l;
    split1(mx,   h, l); d_agh[o + 256 + c] = h; d_agl[o + 256 + c] = l;
    split1(sd,   h, l); d_agh[o + 384 + c] = h; d_agl[o + 384 + c] = l;
}

// h_next = relu(z + y0 + amp*y1 + att*y2 + b2); writes fp32 + bf16 split
__global__ void combine_kernel(const float* __restrict__ b2, float* __restrict__ hout,
                               __nv_bfloat16* __restrict__ hh, __nv_bfloat16* __restrict__ hl) {
    int i = blockIdx.x * blockDim.x + threadIdx.x;
    if (i >= NN * HH) return;
    int node = i >> 7, c = i & 127;
    size_t yo = (size_t)node * 384;
    float v = d_cmb[(size_t)node * 384 + 256 + c] + d_y[yo + c]
            + d_amp[node] * d_y[yo + 128 + c]
            + d_att[node] * d_y[yo + 256 + c] + b2[c];
    v = fmaxf(v, 0.f);
    hout[i] = v;
    __nv_bfloat16 h, l; split1(v, h, l);
    hh[i] = h; hl[i] = l;
}

__global__ void pool_kernel(const float* __restrict__ h, const int* __restrict__ batch) {
    int i = blockIdx.x * blockDim.x + threadIdx.x;
    if (i >= NN * HH) return;
    int node = i >> 7, c = i & 127;
    atomicAdd(&d_g[batch[node] * HH + c], h[i]);
}

__global__ void head_kernel(const float* __restrict__ W, const float* __restrict__ b,
                            float* __restrict__ out) {
    __shared__ float sh[HH];
    sh[threadIdx.x] = d_g[blockIdx.x * HH + threadIdx.x];
    __syncthreads();
    if (threadIdx.x < OUTC) {
        float s = b[threadIdx.x];
        for (int k = 0; k < HH; k++) s = fmaf(sh[k], W[k * OUTC + threadIdx.x], s);
        out[blockIdx.x * OUTC + threadIdx.x] = s;
    }
}

// ---------------- host orchestration ----------------
static void gemm(const float* A, int lda, const float* B, int ldb, float* C, int ldc,
                 int M, int N, int K, const float* bias, const int* perm) {
    dim3 grid(N / 128, (M + 127) / 128);
    sgemm_kernel<<<grid, 256>>>(A, lda, B, ldb, C, ldc, M, N, K, bias, perm);
}

static void tgemm(const __nv_bfloat16* Ah, const __nv_bfloat16* Al,
                  const __nv_bfloat16* Bh, const __nv_bfloat16* Bl,
                  float* C, int ldc, int M, int N, int K, const float* bias) {
    dim3 grid((M + 127) / 128, N / 128);
    hmma_kernel<<<grid, 256, TSMEM>>>(Ah, Al, Bh, Bl, C, ldc, M, K, bias);
}

template <typename T>
static T* sym(const void* symbol) {
    void* p = nullptr;
    cudaGetSymbolAddress(&p, symbol);
    return (T*)p;
}

extern "C" void kernel_launch(void* const* d_in, const int* in_sizes, int n_in,
                              void* d_out, int out_size) {
    const float* x     = (const float*)d_in[0];
    const float* eattr = (const float*)d_in[1];
    const int*   src   = (const int*)  d_in[2];
    const int*   dst   = (const int*)  d_in[3];
    const int*   batch = (const int*)  d_in[4];
    const float* nW    = (const float*)d_in[5];
    const float* nb    = (const float*)d_in[6];
    const float* eW    = (const float*)d_in[7];
    const float* eb    = (const float*)d_in[8];
    const float* encW  = (const float*)d_in[9];
    const float* encb  = (const float*)d_in[10];
    const float* preW  = (const float*)d_in[11];
    const float* preb  = (const float*)d_in[12];
    const float* postW = (const float*)d_in[13];
    const float* postb = (const float*)d_in[14];
    const float* linW  = (const float*)d_in[15];
    const float* linb  = (const float*)d_in[16];
    const float* headW = (const float*)d_in[17];
    const float* headb = (const float*)d_in[18];
    float* out = (float*)d_out;

    float* e0p  = sym<float>(d_e0p);
    __nv_bfloat16* e0h = sym<__nv_bfloat16>(d_e0h);
    __nv_bfloat16* e0l = sym<__nv_bfloat16>(d_e0l);
    float* mE   = sym<float>(d_mE);
    float* cmb  = sym<float>(d_cmb);
    __nv_bfloat16* agh = sym<__nv_bfloat16>(d_agh);
    __nv_bfloat16* agl = sym<__nv_bfloat16>(d_agl);
    float* y    = sym<float>(d_y);
    float* h0   = sym<float>(d_h0);
    float* h1   = sym<float>(d_h1);
    __nv_bfloat16* hh[2] = { sym<__nv_bfloat16>(d_hh0), sym<__nv_bfloat16>(d_hh1) };
    __nv_bfloat16* hl[2] = { sym<__nv_bfloat16>(d_hl0), sym<__nv_bfloat16>(d_hl1) };
    int*   deg  = sym<int>(d_deg);
    int*   offs = sym<int>(d_offs);
    int*   cnt  = sym<int>(d_cnt);
    int*   perm = sym<int>(d_perm);
    float* avg  = sym<float>(d_avg);
    float* R    = sym<float>(d_R);
    float* rb   = sym<float>(d_rb);
    float* Qcat = sym<float>(d_Qcat);
    float* Q0   = sym<float>(d_Q0);
    float* b2   = sym<float>(d_b2);
    float* g    = sym<float>(d_g);
    __nv_bfloat16* Wch = sym<__nv_bfloat16>(d_Wch); __nv_bfloat16* Wcl = sym<__nv_bfloat16>(d_Wcl);
    __nv_bfloat16* Rth = sym<__nv_bfloat16>(d_Rth); __nv_bfloat16* Rtl = sym<__nv_bfloat16>(d_Rtl);
    __nv_bfloat16* Qch = sym<__nv_bfloat16>(d_Qch); __nv_bfloat16* Qcl = sym<__nv_bfloat16>(d_Qcl);

    cudaFuncSetAttribute(hmma_kernel, cudaFuncAttributeMaxDynamicSharedMemorySize, TSMEM);

    const int TPB = 256;

    // ---- graph structure ----
    cudaMemsetAsync(deg, 0, NN * sizeof(int), 0);
    cudaMemsetAsync(avg, 0, sizeof(float), 0);
    count_kernel<<<(EE + TPB - 1) / TPB, TPB>>>(dst, EE);
    scan_kernel<<<1, 1024>>>();
    cudaMemcpyAsync(cnt, offs, NN * sizeof(int), cudaMemcpyDeviceToDevice, 0);
    scatter_kernel<<<(EE + TPB - 1) / TPB, TPB>>>(src, dst, EE);
    logdeg_sum_kernel<<<256, 256>>>();
    scalers_kernel<<<(NN + TPB - 1) / TPB, TPB>>>();

    // ---- embeddings (fp32) + splits ----
    gemm(eattr, EIN, eW, HH, e0p, HH, EE, HH, EIN, eb, perm);
    split_kernel<<<(int)(((long)EE * HH + TPB - 1) / TPB), TPB>>>(e0p, e0h, e0l, (long)EE * HH);
    gemm(x, FIN, nW, HH, h0, HH, NN, HH, FIN, nb, nullptr);
    split_kernel<<<(int)(((long)NN * HH + TPB - 1) / TPB), TPB>>>(h0, hh[0], hl[0], (long)NN * HH);

    // ---- per-layer weight precompute + transpose-convert ----
    for (int l = 0; l < LL; l++) {
        const float* Wenc  = encW + (size_t)l * HH * HH;
        const float* Wpre2 = preW + (size_t)l * 3 * HH * HH + 2 * HH * HH;
        gemm(Wenc, HH, Wpre2, HH, R + (size_t)l * HH * HH, HH, HH, HH, HH, nullptr, nullptr);
        vecmat_kernel<<<1, HH>>>(encb + l * HH, Wpre2, HH, preb + l * HH, rb + l * HH);
        const float* Pl  = postW + (size_t)l * 13 * HH * HH;
        const float* lin = linW + (size_t)l * HH * HH;
        for (int q = 0; q < 3; q++) {
            gemm(Pl + (size_t)(HH + q * 4 * HH) * HH, HH, lin, HH,
                 Qcat + (size_t)l * 4 * HH * 3 * HH + q * HH, 3 * HH,
                 4 * HH, HH, HH, nullptr, nullptr);
        }
        gemm(Pl, HH, lin, HH, Q0 + (size_t)l * HH * HH, HH, HH, HH, HH, nullptr, nullptr);
        vecmat_kernel<<<1, HH>>>(postb + l * HH, lin, HH, linb + l * HH, b2 + l * HH);

        // combined node weights: Wcmb rows 0-127 = W0^T, 128-255 = W1^T, 256-383 = Q0^T
        int nblk = (HH * HH + TPB - 1) / TPB;
        size_t co = (size_t)l * 3 * HH * HH;
        tconv_kernel<<<nblk, TPB>>>(preW + (size_t)l * 3 * HH * HH,
                                    Wch + co, Wcl + co, HH, HH);
        tconv_kernel<<<nblk, TPB>>>(preW + (size_t)l * 3 * HH * HH + HH * HH,
                                    Wch + co + HH * HH, Wcl + co + HH * HH, HH, HH);
        tconv_kernel<<<nblk, TPB>>>(Q0 + (size_t)l * HH * HH,
                                    Wch + co + 2 * HH * HH, Wcl + co + 2 * HH * HH, HH, HH);
        tconv_kernel<<<nblk, TPB>>>(R + (size_t)l * HH * HH,
                                    Rth + (size_t)l * HH * HH, Rtl + (size_t)l * HH * HH, HH, HH);
        int nblk2 = (4 * HH * 3 * HH + TPB - 1) / TPB;
        tconv_kernel<<<nblk2, TPB>>>(Qcat + (size_t)l * 4 * HH * 3 * HH,
                                     Qch + (size_t)l * 3 * HH * 4 * HH,
                                     Qcl + (size_t)l * 3 * HH * 4 * HH, 4 * HH, 3 * HH);
    }

    // ---- layers ----
    float* hcur = h0;
    float* hnext = h1;
    int cb = 0;
    for (int l = 0; l < LL; l++) {
        // cmb = h @ [W0 | W1 | Q0]  -> [hd|hs|z], N=384
        tgemm(hh[cb], hl[cb], Wch + (size_t)l * 3 * HH * HH, Wcl + (size_t)l * 3 * HH * HH,
              cmb, 3 * HH, NN, 3 * HH, HH, nullptr);
        // mE = e0p @ R_l + rb_l (CSR order)
        tgemm(e0h, e0l, Rth + (size_t)l * HH * HH, Rtl + (size_t)l * HH * HH,
              mE, HH, EE, HH, HH, rb + l * HH);
        // segmented aggregation -> agg splits [N,512]
        agg_kernel<<<NN, HH>>>();
        // y = agg @ Qcat_l  [N,384]
        tgemm(agh, agl, Qch + (size_t)l * 3 * HH * 4 * HH, Qcl + (size_t)l * 3 * HH * 4 * HH,
              y, 3 * HH, NN, 3 * HH, 4 * HH, nullptr);
        // combine -> hnext fp32 + splits
        combine_kernel<<<(NN * HH + TPB - 1) / TPB, TPB>>>(b2 + l * HH, hnext,
                                                           hh[cb ^ 1], hl[cb ^ 1]);
        float* t = hcur; hcur = hnext; hnext = t;
        cb ^= 1;
    }

    // ---- pool + head ----
    cudaMemsetAsync(g, 0, GG * HH * sizeof(float), 0);
    pool_kernel<<<(NN * HH + TPB - 1) / TPB, TPB>>>(hcur, batch);
    head_kernel<<<GG, HH>>>(headW, headb, out);
}

// round 5
// speedup vs baseline: 1.8701x; 1.1170x over previous
#include <cuda_runtime.h>
#include <math.h>
#include <stdint.h>
#include <cuda_bf16.h>

// ---------------- problem constants ----------------
static const int NN   = 50000;   // nodes
static const int EE   = 400000;  // edges
static const int FIN  = 64;
static const int EIN  = 16;
static const int HH   = 128;
static const int LL   = 4;
static const int GG   = 256;
static const int OUTC = 12;

// ---------------- scratch (static device globals; no runtime alloc) ----------------
__device__ float d_eap[(size_t)EE * EIN];       // permuted raw edge attrs (CSR order)
__device__ float d_cmb[(size_t)NN * 3 * HH];    // [hd | hs | z] per node
__device__ __nv_bfloat16 d_agh[(size_t)NN * 4 * HH];
__device__ __nv_bfloat16 d_agl[(size_t)NN * 4 * HH];
__device__ float d_y  [(size_t)NN * 3 * HH];    // agg @ Qcat
__device__ float d_h0 [(size_t)NN * HH];
__device__ float d_h1 [(size_t)NN * HH];
__device__ __nv_bfloat16 d_hh0[(size_t)NN * HH];
__device__ __nv_bfloat16 d_hl0[(size_t)NN * HH];
__device__ __nv_bfloat16 d_hh1[(size_t)NN * HH];
__device__ __nv_bfloat16 d_hl1[(size_t)NN * HH];
__device__ int   d_deg [NN];
__device__ int   d_offs[NN + 1];
__device__ int   d_cnt [NN];
__device__ int   d_perm[EE];
__device__ int   d_srcp[EE];
__device__ float d_amp[NN];
__device__ float d_att[NN];
__device__ float d_avg[1];
__device__ float d_S   [LL * EIN * HH];         // eW@Wenc@Wpre2 per layer [16,128]
__device__ float d_T1  [EIN * HH];              // temp
__device__ float d_u   [HH];                    // temp
__device__ float d_tl  [LL * HH];               // edge-path bias per layer
__device__ float d_Qcat[LL * 4 * HH * 3 * HH];  // [512,384] per layer
__device__ float d_Q0  [LL * HH * HH];          // P0@lin
__device__ float d_b2  [LL * HH];               // post_b@lin + lin_b
__device__ float d_g   [GG * HH];
// transposed bf16-split weights (Bt layout: [N,K] row-major)
__device__ __nv_bfloat16 d_Wch[LL * 3 * HH * HH], d_Wcl[LL * 3 * HH * HH];   // [384,128]: W0|W1|Q0
__device__ __nv_bfloat16 d_Qch[LL * 3 * HH * 4 * HH], d_Qcl[LL * 3 * HH * 4 * HH]; // [384,512]

// ================= warp-level bf16 MMA GEMM (mma.sync) =================
// C[M, gridDim.y*128] = A @ Bt^T (+bias). A: bf16 hi/lo [M,K] row-major.
// Bt: bf16 hi/lo [N,K] row-major. bf16x3: D = Ah*Bh + Ah*Bl + Al*Bh. K % 32 == 0.
static const int HPAD = 40;                 // padded K-stride in bf16 (conflict-free ldmatrix)
static const int TILEB = 128 * HPAD * 2;    // 10240 B per tile
static const int BUFB  = 4 * TILEB;         // Ah,Al,Bh,Bl
static const int TSMEM = 2 * BUFB;          // 81920 B

#define LDSM4(R, ADDR) \
    asm volatile("ldmatrix.sync.aligned.m8n8.x4.shared.b16 {%0,%1,%2,%3}, [%4];" \
        : "=r"((R)[0]), "=r"((R)[1]), "=r"((R)[2]), "=r"((R)[3]) : "r"(ADDR))

#define MMA16816(D, A, B) \
    asm volatile("mma.sync.aligned.m16n8k16.row.col.f32.bf16.bf16.f32 " \
        "{%0,%1,%2,%3}, {%4,%5,%6,%7}, {%8,%9}, {%0,%1,%2,%3};" \
        : "+f"((D)[0]), "+f"((D)[1]), "+f"((D)[2]), "+f"((D)[3]) \
        : "r"((A)[0]), "r"((A)[1]), "r"((A)[2]), "r"((A)[3]), "r"((B)[0]), "r"((B)[1]))

__device__ __forceinline__ uint32_t smem_u32(const void* p) {
    uint32_t a;
    asm("{ .reg .u64 t; cvta.to.shared.u64 t, %1; cvt.u32.u64 %0, t; }" : "=r"(a) : "l"(p));
    return a;
}

__global__ void __launch_bounds__(256) hmma_kernel(
    const __nv_bfloat16* __restrict__ Ah, const __nv_bfloat16* __restrict__ Al,
    const __nv_bfloat16* __restrict__ Bh, const __nv_bfloat16* __restrict__ Bl,
    float* __restrict__ C, int ldc, int M, int K,
    const float* __restrict__ bias)
{
    extern __shared__ char smem[];
    const uint32_t sb = smem_u32(smem);
    const int tid = threadIdx.x, lane = tid & 31, wid = tid >> 5;
    const int warp_m = wid & 3, warp_n = wid >> 2;         // 4 x 2 warps
    const int m0 = blockIdx.x * 128, n0 = blockIdx.y * 128;

    const int OAH = 0, OAL = TILEB, OBH = 2 * TILEB, OBL = 3 * TILEB;

    float acc[2][8][4];
#pragma unroll
    for (int i = 0; i < 2; i++)
#pragma unroll
        for (int j = 0; j < 8; j++)
#pragma unroll
            for (int k = 0; k < 4; k++) acc[i][j][k] = 0.f;

    const int ldr = tid >> 2;            // 0..63
    const int ldc8 = (tid & 3) * 8;      // bf16 col: 0,8,16,24
    auto issue_chunk = [&](int buf, int k0) {
        uint32_t bo = sb + buf * BUFB;
#pragma unroll
        for (int half = 0; half < 2; half++) {
            int r = half * 64 + ldr;
            uint32_t soff = (uint32_t)(r * HPAD + ldc8) * 2;
            int arow = m0 + r;
            int asz = (arow < M) ? 16 : 0;
            const void* gah = Ah + (size_t)arow * K + k0 + ldc8;
            const void* gal = Al + (size_t)arow * K + k0 + ldc8;
            asm volatile("cp.async.cg.shared.global [%0], [%1], 16, %2;"
                         :: "r"(bo + OAH + soff), "l"(gah), "r"(asz));
            asm volatile("cp.async.cg.shared.global [%0], [%1], 16, %2;"
                         :: "r"(bo + OAL + soff), "l"(gal), "r"(asz));
            const void* gbh = Bh + (size_t)(n0 + r) * K + k0 + ldc8;
            const void* gbl = Bl + (size_t)(n0 + r) * K + k0 + ldc8;
            asm volatile("cp.async.cg.shared.global [%0], [%1], 16;"
                         :: "r"(bo + OBH + soff), "l"(gbh));
            asm volatile("cp.async.cg.shared.global [%0], [%1], 16;"
                         :: "r"(bo + OBL + soff), "l"(gbl));
        }
        asm volatile("cp.async.commit_group;");
    };

    const int a_r  = lane & 15;
    const int a_kg = (lane >> 4) * 8;
    const int b_r  = (lane & 7) + ((lane >> 4) * 8);
    const int b_kg = ((lane >> 3) & 1) * 8;

    const int nchunks = K >> 5;
    issue_chunk(0, 0);

    for (int ch = 0; ch < nchunks; ch++) {
        asm volatile("cp.async.wait_group 0;");
        __syncthreads();
        if (ch + 1 < nchunks) issue_chunk((ch + 1) & 1, (ch + 1) << 5);

        uint32_t bo = sb + (ch & 1) * BUFB;
#pragma unroll
        for (int ks = 0; ks < 2; ks++) {
            int kc = ks * 16;
            uint32_t afh[2][4], afl[2][4], bfh[4][4], bfl[4][4];
#pragma unroll
            for (int mt = 0; mt < 2; mt++) {
                int row = warp_m * 32 + mt * 16 + a_r;
                uint32_t ad = bo + (uint32_t)(row * HPAD + kc + a_kg) * 2;
                LDSM4(afh[mt], ad + OAH);
                LDSM4(afl[mt], ad + OAL);
            }
#pragma unroll
            for (int np = 0; np < 4; np++) {
                int nrow = warp_n * 64 + np * 16 + b_r;
                uint32_t bd = bo + (uint32_t)(nrow * HPAD + kc + b_kg) * 2;
                LDSM4(bfh[np], bd + OBH);
                LDSM4(bfl[np], bd + OBL);
            }
#pragma unroll
            for (int mt = 0; mt < 2; mt++)
#pragma unroll
                for (int np = 0; np < 4; np++) {
                    MMA16816(acc[mt][np * 2 + 0], afh[mt], (&bfh[np][0]));
                    MMA16816(acc[mt][np * 2 + 1], afh[mt], (&bfh[np][2]));
                    MMA16816(acc[mt][np * 2 + 0], afl[mt], (&bfh[np][0]));
                    MMA16816(acc[mt][np * 2 + 1], afl[mt], (&bfh[np][2]));
                    MMA16816(acc[mt][np * 2 + 0], afh[mt], (&bfl[np][0]));
                    MMA16816(acc[mt][np * 2 + 1], afh[mt], (&bfl[np][2]));
                }
        }
    }

    const int mrow = m0 + warp_m * 32;
    const int ncol = n0 + warp_n * 64;
#pragma unroll
    for (int mt = 0; mt < 2; mt++) {
#pragma unroll
        for (int nt = 0; nt < 8; nt++) {
            int c = ncol + nt * 8 + (lane & 3) * 2;
            float2 bv = bias ? *(const float2*)&bias[c] : make_float2(0.f, 0.f);
            int r0 = mrow + mt * 16 + (lane >> 2);
            if (r0 < M) {
                float2 v = make_float2(acc[mt][nt][0] + bv.x, acc[mt][nt][1] + bv.y);
                *(float2*)&C[(size_t)r0 * ldc + c] = v;
            }
            int r1 = r0 + 8;
            if (r1 < M) {
                float2 v = make_float2(acc[mt][nt][2] + bv.x, acc[mt][nt][3] + bv.y);
                *(float2*)&C[(size_t)r1 * ldc + c] = v;
            }
        }
    }
}

// ---------------- split / transpose-convert helpers ----------------
__device__ __forceinline__ void split1(float x, __nv_bfloat16& h, __nv_bfloat16& l) {
    h = __float2bfloat16(x);
    l = __float2bfloat16(x - __bfloat162float(h));
}

__global__ void split_kernel(const float* __restrict__ in,
                             __nv_bfloat16* __restrict__ hi,
                             __nv_bfloat16* __restrict__ lo, long n) {
    long i = (long)blockIdx.x * blockDim.x + threadIdx.x;
    if (i < n) { __nv_bfloat16 h, l; split1(in[i], h, l); hi[i] = h; lo[i] = l; }
}

// in [K,N] fp32 row-major -> out hi/lo [N,K] bf16 row-major
__global__ void tconv_kernel(const float* __restrict__ in,
                             __nv_bfloat16* __restrict__ hi,
                             __nv_bfloat16* __restrict__ lo, int K, int N) {
    int i = blockIdx.x * blockDim.x + threadIdx.x;
    if (i < K * N) {
        int n = i / K, k = i - n * K;
        __nv_bfloat16 h, l; split1(in[(size_t)k * N + n], h, l);
        hi[(size_t)n * K + k] = h; lo[(size_t)n * K + k] = l;
    }
}

// ---------------- fp32 SGEMM (embeddings + small precompute) ----------------
__global__ void __launch_bounds__(256) sgemm_kernel(
    const float* __restrict__ A, int lda,
    const float* __restrict__ B, int ldb,
    float* __restrict__ C, int ldc,
    int M, int N, int K,
    const float* __restrict__ bias,
    const int* __restrict__ perm)
{
    const int BM = 128, BN = 128, BK = 8;
    __shared__ float As[BK][BM];
    __shared__ float Bs[BK][BN];
    int tid = threadIdx.x;
    int brow = blockIdx.y, bcol = blockIdx.x;
    int aRow = tid >> 1, aCol4 = (tid & 1) * 4;
    int bRow = tid >> 5, bCol4 = (tid & 31) * 4;
    int tr = (tid >> 4) * 8, tc = (tid & 15) * 8;
    float acc[8][8];
#pragma unroll
    for (int i = 0; i < 8; i++)
#pragma unroll
        for (int j = 0; j < 8; j++) acc[i][j] = 0.f;
    int gArow = brow * BM + aRow;
    bool aValid = gArow < M;
    long arow_idx = 0;
    if (aValid) arow_idx = perm ? (long)perm[gArow] : (long)gArow;
    const float* Aptr = A + arow_idx * (long)lda + aCol4;
    const float* Bptr = B + (long)bRow * ldb + (long)bcol * BN + bCol4;
    for (int k0 = 0; k0 < K; k0 += BK) {
        float4 av = aValid ? *(const float4*)(Aptr + k0) : make_float4(0.f, 0.f, 0.f, 0.f);
        float4 bv = *(const float4*)(Bptr + (long)k0 * ldb);
        As[aCol4 + 0][aRow] = av.x; As[aCol4 + 1][aRow] = av.y;
        As[aCol4 + 2][aRow] = av.z; As[aCol4 + 3][aRow] = av.w;
        *(float4*)&Bs[bRow][bCol4] = bv;
        __syncthreads();
#pragma unroll
        for (int kk = 0; kk < BK; kk++) {
            float ar[8], br[8];
#pragma unroll
            for (int i = 0; i < 8; i++) ar[i] = As[kk][tr + i];
#pragma unroll
            for (int j = 0; j < 8; j++) br[j] = Bs[kk][tc + j];
#pragma unroll
            for (int i = 0; i < 8; i++)
#pragma unroll
                for (int j = 0; j < 8; j++)
                    acc[i][j] = fmaf(ar[i], br[j], acc[i][j]);
        }
        __syncthreads();
    }
#pragma unroll
    for (int i = 0; i < 8; i++) {
        int row = brow * BM + tr + i;
        if (row < M) {
#pragma unroll
            for (int j = 0; j < 8; j += 4) {
                int col = bcol * BN + tc + j;
                float4 v;
                v.x = acc[i][j + 0] + (bias ? bias[col + 0] : 0.f);
                v.y = acc[i][j + 1] + (bias ? bias[col + 1] : 0.f);
                v.z = acc[i][j + 2] + (bias ? bias[col + 2] : 0.f);
                v.w = acc[i][j + 3] + (bias ? bias[col + 3] : 0.f);
                *(float4*)&C[(long)row * ldc + col] = v;
            }
        }
    }
}

// ---------------- small helper kernels ----------------
__global__ void count_kernel(const int* __restrict__ dst, int n) {
    int i = blockIdx.x * blockDim.x + threadIdx.x;
    if (i < n) atomicAdd(&d_deg[dst[i]], 1);
}

__global__ void scan_kernel() {
    __shared__ int sh[1024];
    __shared__ int carry;
    if (threadIdx.x == 0) carry = 0;
    __syncthreads();
    for (int base = 0; base < NN; base += 1024) {
        int i = base + (int)threadIdx.x;
        int v = (i < NN) ? d_deg[i] : 0;
        sh[threadIdx.x] = v;
        __syncthreads();
        for (int off = 1; off < 1024; off <<= 1) {
            int t = (threadIdx.x >= (unsigned)off) ? sh[threadIdx.x - off] : 0;
            __syncthreads();
            sh[threadIdx.x] += t;
            __syncthreads();
        }
        if (i < NN) d_offs[i] = carry + sh[threadIdx.x] - v;
        __syncthreads();
        if (threadIdx.x == 1023) carry += sh[1023];
        __syncthreads();
    }
    if (threadIdx.x == 0) d_offs[NN] = carry;
}

__global__ void scatter_kernel(const int* __restrict__ src, const int* __restrict__ dst, int n) {
    int i = blockIdx.x * blockDim.x + threadIdx.x;
    if (i < n) {
        int pos = atomicAdd(&d_cnt[dst[i]], 1);
        d_perm[pos] = i;
        d_srcp[pos] = src[i];
    }
}

// gather permuted raw edge attrs (CSR order), 16 floats per edge
__global__ void gather_eattr_kernel(const float* __restrict__ ea) {
    int i = blockIdx.x * blockDim.x + threadIdx.x;
    if (i < EE) {
        int e = d_perm[i];
        float4* dst = (float4*)(d_eap + (size_t)i * EIN);
        const float4* s = (const float4*)(ea + (size_t)e * EIN);
        dst[0] = s[0]; dst[1] = s[1]; dst[2] = s[2]; dst[3] = s[3];
    }
}

__global__ void logdeg_sum_kernel() {
    __shared__ float sh[256];
    float s = 0.f;
    for (int i = blockIdx.x * blockDim.x + threadIdx.x; i < NN; i += gridDim.x * blockDim.x)
        s += log1pf((float)d_deg[i]);
    sh[threadIdx.x] = s;
    __syncthreads();
    for (int off = 128; off > 0; off >>= 1) {
        if (threadIdx.x < (unsigned)off) sh[threadIdx.x] += sh[threadIdx.x + off];
        __syncthreads();
    }
    if (threadIdx.x == 0) atomicAdd(&d_avg[0], sh[0]);
}

__global__ void scalers_kernel() {
    int i = blockIdx.x * blockDim.x + threadIdx.x;
    if (i < NN) {
        float avg  = d_avg[0] / (float)NN;
        float degc = fmaxf((float)d_deg[i], 1.f);
        float l    = logf(degc + 1.f);
        d_amp[i] = l / avg;
        d_att[i] = avg / l;
    }
}

__global__ void vecmat_kernel(const float* __restrict__ v, const float* __restrict__ W, int ldw,
                              const float* __restrict__ badd, float* __restrict__ out) {
    int c = threadIdx.x;
    float s = 0.f;
    for (int j = 0; j < HH; j++) s = fmaf(v[j], W[j * ldw + c], s);
    out[c] = s + badd[c];
}

// segmented aggregation with fused rank-16 edge message.
// m[c] = hd[c] + t[c] + hs[src][c] + sum_{k<16} eattr_p[r][k]*S[k][c]  (all fp32)
__global__ void agg_kernel(const float* __restrict__ S, const float* __restrict__ t) {
    int node = blockIdx.x;
    int c = threadIdx.x;
    float Sreg[16];
#pragma unroll
    for (int k = 0; k < 16; k++) Sreg[k] = S[k * HH + c];   // coalesced
    int s = d_offs[node], e = d_offs[node + 1];
    float hd = d_cmb[(size_t)node * 384 + c] + t[c];
    float sum = 0.f, ss = 0.f, mn = INFINITY, mx = -INFINITY;
    for (int r = s; r < e; r++) {
        int sp = d_srcp[r];
        const float4* ea = (const float4*)(d_eap + (size_t)r * EIN);
        float4 e0 = ea[0], e1 = ea[1], e2 = ea[2], e3 = ea[3];
        float v = hd + d_cmb[(size_t)sp * 384 + 128 + c];
        v = fmaf(e0.x, Sreg[0],  v); v = fmaf(e0.y, Sreg[1],  v);
        v = fmaf(e0.z, Sreg[2],  v); v = fmaf(e0.w, Sreg[3],  v);
        v = fmaf(e1.x, Sreg[4],  v); v = fmaf(e1.y, Sreg[5],  v);
        v = fmaf(e1.z, Sreg[6],  v); v = fmaf(e1.w, Sreg[7],  v);
        v = fmaf(e2.x, Sreg[8],  v); v = fmaf(e2.y, Sreg[9],  v);
        v = fmaf(e2.z, Sreg[10], v); v = fmaf(e2.w, Sreg[11], v);
        v = fmaf(e3.x, Sreg[12], v); v = fmaf(e3.y, Sreg[13], v);
        v = fmaf(e3.z, Sreg[14], v); v = fmaf(e3.w, Sreg[15], v);
        sum += v;
        ss  = fmaf(v, v, ss);
        mn  = fminf(mn, v);
        mx  = fmaxf(mx, v);
    }
    float deg  = (float)(e - s);
    float degc = fmaxf(deg, 1.f);
    float mean = sum / degc;
    float var  = ss / degc - mean * mean;
    float sd   = sqrtf(fmaxf(var, 0.f) + 1e-5f);
    if (e == s) { mn = 0.f; mx = 0.f; }
    size_t o = (size_t)node * 512;
    __nv_bfloat16 h, l;
    split1(mean, h, l); d_agh[o +       c] = h; d_agl[o +       c] = l;
    split1(mn,   h, l); d_agh[o + 128 + c] = h; d_agl[o + 128 + c] = l;
    split1(mx,   h, l); d_agh[o + 256 + c] = h; d_agl[o + 256 + c] = l;
    split1(sd,   h, l); d_agh[o + 384 + c] = h; d_agl[o + 384 + c] = l;
}

// h_next = relu(z + y0 + amp*y1 + att*y2 + b2); writes fp32 + bf16 split
__global__ void combine_kernel(const float* __restrict__ b2, float* __restrict__ hout,
                               __nv_bfloat16* __restrict__ hh, __nv_bfloat16* __restrict__ hl) {
    int i = blockIdx.x * blockDim.x + threadIdx.x;
    if (i >= NN * HH) return;
    int node = i >> 7, c = i & 127;
    size_t yo = (size_t)node * 384;
    float v = d_cmb[(size_t)node * 384 + 256 + c] + d_y[yo + c]
            + d_amp[node] * d_y[yo + 128 + c]
            + d_att[node] * d_y[yo + 256 + c] + b2[c];
    v = fmaxf(v, 0.f);
    hout[i] = v;
    __nv_bfloat16 h, l; split1(v, h, l);
    hh[i] = h; hl[i] = l;
}

__global__ void pool_kernel(const float* __restrict__ h, const int* __restrict__ batch) {
    int i = blockIdx.x * blockDim.x + threadIdx.x;
    if (i >= NN * HH) return;
    int node = i >> 7, c = i & 127;
    atomicAdd(&d_g[batch[node] * HH + c], h[i]);
}

__global__ void head_kernel(const float* __restrict__ W, const float* __restrict__ b,
                            float* __restrict__ out) {
    __shared__ float sh[HH];
    sh[threadIdx.x] = d_g[blockIdx.x * HH + threadIdx.x];
    __syncthreads();
    if (threadIdx.x < OUTC) {
        float s = b[threadIdx.x];
        for (int k = 0; k < HH; k++) s = fmaf(sh[k], W[k * OUTC + threadIdx.x], s);
        out[blockIdx.x * OUTC + threadIdx.x] = s;
    }
}

// ---------------- host orchestration ----------------
static void gemm(const float* A, int lda, const float* B, int ldb, float* C, int ldc,
                 int M, int N, int K, const float* bias, const int* perm) {
    dim3 grid(N / 128, (M + 127) / 128);
    sgemm_kernel<<<grid, 256>>>(A, lda, B, ldb, C, ldc, M, N, K, bias, perm);
}

static void tgemm(const __nv_bfloat16* Ah, const __nv_bfloat16* Al,
                  const __nv_bfloat16* Bh, const __nv_bfloat16* Bl,
                  float* C, int ldc, int M, int N, int K, const float* bias) {
    dim3 grid((M + 127) / 128, N / 128);
    hmma_kernel<<<grid, 256, TSMEM>>>(Ah, Al, Bh, Bl, C, ldc, M, K, bias);
}

template <typename T>
static T* sym(const void* symbol) {
    void* p = nullptr;
    cudaGetSymbolAddress(&p, symbol);
    return (T*)p;
}

extern "C" void kernel_launch(void* const* d_in, const int* in_sizes, int n_in,
                              void* d_out, int out_size) {
    const float* x     = (const float*)d_in[0];
    const float* eattr = (const float*)d_in[1];
    const int*   src   = (const int*)  d_in[2];
    const int*   dst   = (const int*)  d_in[3];
    const int*   batch = (const int*)  d_in[4];
    const float* nW    = (const float*)d_in[5];
    const float* nb    = (const float*)d_in[6];
    const float* eW    = (const float*)d_in[7];
    const float* eb    = (const float*)d_in[8];
    const float* encW  = (const float*)d_in[9];
    const float* encb  = (const float*)d_in[10];
    const float* preW  = (const float*)d_in[11];
    const float* preb  = (const float*)d_in[12];
    const float* postW = (const float*)d_in[13];
    const float* postb = (const float*)d_in[14];
    const float* linW  = (const float*)d_in[15];
    const float* linb  = (const float*)d_in[16];
    const float* headW = (const float*)d_in[17];
    const float* headb = (const float*)d_in[18];
    float* out = (float*)d_out;

    float* eap  = sym<float>(d_eap);
    float* cmb  = sym<float>(d_cmb);
    __nv_bfloat16* agh = sym<__nv_bfloat16>(d_agh);
    __nv_bfloat16* agl = sym<__nv_bfloat16>(d_agl);
    float* y    = sym<float>(d_y);
    float* h0   = sym<float>(d_h0);
    float* h1   = sym<float>(d_h1);
    __nv_bfloat16* hh[2] = { sym<__nv_bfloat16>(d_hh0), sym<__nv_bfloat16>(d_hh1) };
    __nv_bfloat16* hl[2] = { sym<__nv_bfloat16>(d_hl0), sym<__nv_bfloat16>(d_hl1) };
    int*   deg  = sym<int>(d_deg);
    int*   offs = sym<int>(d_offs);
    int*   cnt  = sym<int>(d_cnt);
    float* avg  = sym<float>(d_avg);
    float* S    = sym<float>(d_S);
    float* T1   = sym<float>(d_T1);
    float* u    = sym<float>(d_u);
    float* tl   = sym<float>(d_tl);
    float* Qcat = sym<float>(d_Qcat);
    float* Q0   = sym<float>(d_Q0);
    float* b2   = sym<float>(d_b2);
    float* g    = sym<float>(d_g);
    __nv_bfloat16* Wch = sym<__nv_bfloat16>(d_Wch); __nv_bfloat16* Wcl = sym<__nv_bfloat16>(d_Wcl);
    __nv_bfloat16* Qch = sym<__nv_bfloat16>(d_Qch); __nv_bfloat16* Qcl = sym<__nv_bfloat16>(d_Qcl);

    cudaFuncSetAttribute(hmma_kernel, cudaFuncAttributeMaxDynamicSharedMemorySize, TSMEM);

    const int TPB = 256;

    // ---- graph structure ----
    cudaMemsetAsync(deg, 0, NN * sizeof(int), 0);
    cudaMemsetAsync(avg, 0, sizeof(float), 0);
    count_kernel<<<(EE + TPB - 1) / TPB, TPB>>>(dst, EE);
    scan_kernel<<<1, 1024>>>();
    cudaMemcpyAsync(cnt, offs, NN * sizeof(int), cudaMemcpyDeviceToDevice, 0);
    scatter_kernel<<<(EE + TPB - 1) / TPB, TPB>>>(src, dst, EE);
    gather_eattr_kernel<<<(EE + TPB - 1) / TPB, TPB>>>(eattr);
    logdeg_sum_kernel<<<256, 256>>>();
    scalers_kernel<<<(NN + TPB - 1) / TPB, TPB>>>();

    // ---- node embedding (fp32) + split ----
    gemm(x, FIN, nW, HH, h0, HH, NN, HH, FIN, nb, nullptr);
    split_kernel<<<(int)(((long)NN * HH + TPB - 1) / TPB), TPB>>>(h0, hh[0], hl[0], (long)NN * HH);

    // ---- per-layer weight precompute ----
    for (int l = 0; l < LL; l++) {
        const float* Wenc  = encW + (size_t)l * HH * HH;
        const float* Wpre2 = preW + (size_t)l * 3 * HH * HH + 2 * HH * HH;
        // S_l = eW @ Wenc @ Wpre2  [16,128]
        gemm(eW, HH, Wenc, HH, T1, HH, EIN, HH, HH, nullptr, nullptr);
        gemm(T1, HH, Wpre2, HH, S + (size_t)l * EIN * HH, HH, EIN, HH, HH, nullptr, nullptr);
        // t_l = (eb@Wenc + encb) @ Wpre2 + preb
        vecmat_kernel<<<1, HH>>>(eb, Wenc, HH, encb + l * HH, u);
        vecmat_kernel<<<1, HH>>>(u, Wpre2, HH, preb + l * HH, tl + l * HH);

        const float* Pl  = postW + (size_t)l * 13 * HH * HH;
        const float* lin = linW + (size_t)l * HH * HH;
        for (int q = 0; q < 3; q++) {
            gemm(Pl + (size_t)(HH + q * 4 * HH) * HH, HH, lin, HH,
                 Qcat + (size_t)l * 4 * HH * 3 * HH + q * HH, 3 * HH,
                 4 * HH, HH, HH, nullptr, nullptr);
        }
        gemm(Pl, HH, lin, HH, Q0 + (size_t)l * HH * HH, HH, HH, HH, HH, nullptr, nullptr);
        vecmat_kernel<<<1, HH>>>(postb + l * HH, lin, HH, linb + l * HH, b2 + l * HH);

        // combined node weights: rows 0-127 = W0^T, 128-255 = W1^T, 256-383 = Q0^T
        int nblk = (HH * HH + TPB - 1) / TPB;
        size_t co = (size_t)l * 3 * HH * HH;
        tconv_kernel<<<nblk, TPB>>>(preW + (size_t)l * 3 * HH * HH,
                                    Wch + co, Wcl + co, HH, HH);
        tconv_kernel<<<nblk, TPB>>>(preW + (size_t)l * 3 * HH * HH + HH * HH,
                                    Wch + co + HH * HH, Wcl + co + HH * HH, HH, HH);
        tconv_kernel<<<nblk, TPB>>>(Q0 + (size_t)l * HH * HH,
                                    Wch + co + 2 * HH * HH, Wcl + co + 2 * HH * HH, HH, HH);
        int nblk2 = (4 * HH * 3 * HH + TPB - 1) / TPB;
        tconv_kernel<<<nblk2, TPB>>>(Qcat + (size_t)l * 4 * HH * 3 * HH,
                                     Qch + (size_t)l * 3 * HH * 4 * HH,
                                     Qcl + (size_t)l * 3 * HH * 4 * HH, 4 * HH, 3 * HH);
    }

    // ---- layers ----
    float* hcur = h0;
    float* hnext = h1;
    int cb = 0;
    for (int l = 0; l < LL; l++) {
        // cmb = h @ [W0 | W1 | Q0]  -> [hd|hs|z], N=384
        tgemm(hh[cb], hl[cb], Wch + (size_t)l * 3 * HH * HH, Wcl + (size_t)l * 3 * HH * HH,
              cmb, 3 * HH, NN, 3 * HH, HH, nullptr);
        // segmented aggregation with fused rank-16 edge message -> agg splits [N,512]
        agg_kernel<<<NN, HH>>>(S + (size_t)l * EIN * HH, tl + l * HH);
        // y = agg @ Qcat_l  [N,384]
        tgemm(agh, agl, Qch + (size_t)l * 3 * HH * 4 * HH, Qcl + (size_t)l * 3 * HH * 4 * HH,
              y, 3 * HH, NN, 3 * HH, 4 * HH, nullptr);
        // combine -> hnext fp32 + splits
        combine_kernel<<<(NN * HH + TPB - 1) / TPB, TPB>>>(b2 + l * HH, hnext,
                                                           hh[cb ^ 1], hl[cb ^ 1]);
        float* t = hcur; hcur = hnext; hnext = t;
        cb ^= 1;
    }

    // ---- pool + head ----
    cudaMemsetAsync(g, 0, GG * HH * sizeof(float), 0);
    pool_kernel<<<(NN * HH + TPB - 1) / TPB, TPB>>>(hcur, batch);
    head_kernel<<<GG, HH>>>(headW, headb, out);
}

// round 6
// speedup vs baseline: 2.0090x; 1.0743x over previous
#include <cuda_runtime.h>
#include <math.h>
#include <stdint.h>
#include <cuda_bf16.h>

// ---------------- problem constants ----------------
static const int NN   = 50000;   // nodes
static const int EE   = 400000;  // edges
static const int FIN  = 64;
static const int EIN  = 16;
static const int HH   = 128;
static const int LL   = 4;
static const int GG   = 256;
static const int OUTC = 12;

// ---------------- scratch (static device globals; no runtime alloc) ----------------
__device__ float d_eap[(size_t)EE * EIN];       // permuted raw edge attrs (CSR order)
__device__ float d_cmb[(size_t)NN * 3 * HH];    // [hd | hs | z] per node
__device__ __nv_bfloat16 d_agh[(size_t)NN * 4 * HH];
__device__ __nv_bfloat16 d_agl[(size_t)NN * 4 * HH];
__device__ float d_y  [(size_t)NN * 3 * HH];    // agg @ Qcat
__device__ float d_h0 [(size_t)NN * HH];
__device__ float d_h1 [(size_t)NN * HH];
__device__ __nv_bfloat16 d_hh0[(size_t)NN * HH];
__device__ __nv_bfloat16 d_hl0[(size_t)NN * HH];
__device__ __nv_bfloat16 d_hh1[(size_t)NN * HH];
__device__ __nv_bfloat16 d_hl1[(size_t)NN * HH];
__device__ int   d_deg [NN];
__device__ int   d_offs[NN + 1];
__device__ int   d_cnt [NN];
__device__ int   d_perm[EE];
__device__ int   d_srcp[EE];
__device__ float d_amp[NN];
__device__ float d_att[NN];
__device__ float d_avg[1];
__device__ float d_S   [LL * EIN * HH];         // eW@Wenc@Wpre2 per layer [16,128]
__device__ float d_T1  [EIN * HH];              // temp
__device__ float d_u   [HH];                    // temp
__device__ float d_tl  [LL * HH];               // edge-path bias per layer
__device__ float d_Qcat[LL * 4 * HH * 3 * HH];  // [512,384] per layer
__device__ float d_Q0  [LL * HH * HH];          // P0@lin
__device__ float d_b2  [LL * HH];               // post_b@lin + lin_b
__device__ float d_g   [GG * HH];
// transposed bf16-split weights (Bt layout: [N,K] row-major)
__device__ __nv_bfloat16 d_Wch[LL * 3 * HH * HH], d_Wcl[LL * 3 * HH * HH];   // [384,128]: W0|W1|Q0
__device__ __nv_bfloat16 d_Qch[LL * 3 * HH * 4 * HH], d_Qcl[LL * 3 * HH * 4 * HH]; // [384,512]

// ================= warp-level bf16 MMA GEMM (mma.sync) =================
// C[M, gridDim.y*128] = A @ Bt^T (+bias). A: bf16 hi/lo [M,K] row-major.
// Bt: bf16 hi/lo [N,K] row-major. bf16x3: D = Ah*Bh + Ah*Bl + Al*Bh. K % 32 == 0.
static const int HPAD = 40;                 // padded K-stride in bf16 (conflict-free ldmatrix)
static const int TILEB = 128 * HPAD * 2;    // 10240 B per tile
static const int BUFB  = 4 * TILEB;         // Ah,Al,Bh,Bl
static const int TSMEM = 2 * BUFB;          // 81920 B

#define LDSM4(R, ADDR) \
    asm volatile("ldmatrix.sync.aligned.m8n8.x4.shared.b16 {%0,%1,%2,%3}, [%4];" \
        : "=r"((R)[0]), "=r"((R)[1]), "=r"((R)[2]), "=r"((R)[3]) : "r"(ADDR))

#define MMA16816(D, A, B) \
    asm volatile("mma.sync.aligned.m16n8k16.row.col.f32.bf16.bf16.f32 " \
        "{%0,%1,%2,%3}, {%4,%5,%6,%7}, {%8,%9}, {%0,%1,%2,%3};" \
        : "+f"((D)[0]), "+f"((D)[1]), "+f"((D)[2]), "+f"((D)[3]) \
        : "r"((A)[0]), "r"((A)[1]), "r"((A)[2]), "r"((A)[3]), "r"((B)[0]), "r"((B)[1]))

__device__ __forceinline__ uint32_t smem_u32(const void* p) {
    uint32_t a;
    asm("{ .reg .u64 t; cvta.to.shared.u64 t, %1; cvt.u32.u64 %0, t; }" : "=r"(a) : "l"(p));
    return a;
}

__global__ void __launch_bounds__(256, 2) hmma_kernel(
    const __nv_bfloat16* __restrict__ Ah, const __nv_bfloat16* __restrict__ Al,
    const __nv_bfloat16* __restrict__ Bh, const __nv_bfloat16* __restrict__ Bl,
    float* __restrict__ C, int ldc, int M, int K,
    const float* __restrict__ bias)
{
    extern __shared__ char smem[];
    const uint32_t sb = smem_u32(smem);
    const int tid = threadIdx.x, lane = tid & 31, wid = tid >> 5;
    const int warp_m = wid & 3, warp_n = wid >> 2;         // 4 x 2 warps
    const int m0 = blockIdx.x * 128, n0 = blockIdx.y * 128;

    const int OAH = 0, OAL = TILEB, OBH = 2 * TILEB, OBL = 3 * TILEB;

    float acc[2][8][4];
#pragma unroll
    for (int i = 0; i < 2; i++)
#pragma unroll
        for (int j = 0; j < 8; j++)
#pragma unroll
            for (int k = 0; k < 4; k++) acc[i][j][k] = 0.f;

    const int ldr = tid >> 2;            // 0..63
    const int ldc8 = (tid & 3) * 8;      // bf16 col: 0,8,16,24
    auto issue_chunk = [&](int buf, int k0) {
        uint32_t bo = sb + buf * BUFB;
#pragma unroll
        for (int half = 0; half < 2; half++) {
            int r = half * 64 + ldr;
            uint32_t soff = (uint32_t)(r * HPAD + ldc8) * 2;
            int arow = m0 + r;
            int asz = (arow < M) ? 16 : 0;
            const void* gah = Ah + (size_t)arow * K + k0 + ldc8;
            const void* gal = Al + (size_t)arow * K + k0 + ldc8;
            asm volatile("cp.async.cg.shared.global [%0], [%1], 16, %2;"
                         :: "r"(bo + OAH + soff), "l"(gah), "r"(asz));
            asm volatile("cp.async.cg.shared.global [%0], [%1], 16, %2;"
                         :: "r"(bo + OAL + soff), "l"(gal), "r"(asz));
            const void* gbh = Bh + (size_t)(n0 + r) * K + k0 + ldc8;
            const void* gbl = Bl + (size_t)(n0 + r) * K + k0 + ldc8;
            asm volatile("cp.async.cg.shared.global [%0], [%1], 16;"
                         :: "r"(bo + OBH + soff), "l"(gbh));
            asm volatile("cp.async.cg.shared.global [%0], [%1], 16;"
                         :: "r"(bo + OBL + soff), "l"(gbl));
        }
        asm volatile("cp.async.commit_group;");
    };

    const int a_r  = lane & 15;
    const int a_kg = (lane >> 4) * 8;
    const int b_r  = (lane & 7) + ((lane >> 4) * 8);
    const int b_kg = ((lane >> 3) & 1) * 8;

    const int nchunks = K >> 5;
    issue_chunk(0, 0);

    for (int ch = 0; ch < nchunks; ch++) {
        asm volatile("cp.async.wait_group 0;");
        __syncthreads();
        if (ch + 1 < nchunks) issue_chunk((ch + 1) & 1, (ch + 1) << 5);

        uint32_t bo = sb + (ch & 1) * BUFB;
#pragma unroll
        for (int ks = 0; ks < 2; ks++) {
            int kc = ks * 16;
            uint32_t afh[2][4], afl[2][4];
#pragma unroll
            for (int mt = 0; mt < 2; mt++) {
                int row = warp_m * 32 + mt * 16 + a_r;
                uint32_t ad = bo + (uint32_t)(row * HPAD + kc + a_kg) * 2;
                LDSM4(afh[mt], ad + OAH);
                LDSM4(afl[mt], ad + OAL);
            }
            // np outer, B fragments loaded per-np (keeps live regs ~110, fits 2 CTAs/SM)
#pragma unroll
            for (int np = 0; np < 4; np++) {
                uint32_t bfh[4], bfl[4];
                int nrow = warp_n * 64 + np * 16 + b_r;
                uint32_t bd = bo + (uint32_t)(nrow * HPAD + kc + b_kg) * 2;
                LDSM4(bfh, bd + OBH);
                LDSM4(bfl, bd + OBL);
#pragma unroll
                for (int mt = 0; mt < 2; mt++) {
                    MMA16816(acc[mt][np * 2 + 0], afh[mt], (&bfh[0]));
                    MMA16816(acc[mt][np * 2 + 1], afh[mt], (&bfh[2]));
                    MMA16816(acc[mt][np * 2 + 0], afl[mt], (&bfh[0]));
                    MMA16816(acc[mt][np * 2 + 1], afl[mt], (&bfh[2]));
                    MMA16816(acc[mt][np * 2 + 0], afh[mt], (&bfl[0]));
                    MMA16816(acc[mt][np * 2 + 1], afh[mt], (&bfl[2]));
                }
            }
        }
    }

    const int mrow = m0 + warp_m * 32;
    const int ncol = n0 + warp_n * 64;
#pragma unroll
    for (int mt = 0; mt < 2; mt++) {
#pragma unroll
        for (int nt = 0; nt < 8; nt++) {
            int c = ncol + nt * 8 + (lane & 3) * 2;
            float2 bv = bias ? *(const float2*)&bias[c] : make_float2(0.f, 0.f);
            int r0 = mrow + mt * 16 + (lane >> 2);
            if (r0 < M) {
                float2 v = make_float2(acc[mt][nt][0] + bv.x, acc[mt][nt][1] + bv.y);
                *(float2*)&C[(size_t)r0 * ldc + c] = v;
            }
            int r1 = r0 + 8;
            if (r1 < M) {
                float2 v = make_float2(acc[mt][nt][2] + bv.x, acc[mt][nt][3] + bv.y);
                *(float2*)&C[(size_t)r1 * ldc + c] = v;
            }
        }
    }
}

// ---------------- split / transpose-convert helpers ----------------
__device__ __forceinline__ void split1(float x, __nv_bfloat16& h, __nv_bfloat16& l) {
    h = __float2bfloat16(x);
    l = __float2bfloat16(x - __bfloat162float(h));
}

__global__ void split_kernel(const float* __restrict__ in,
                             __nv_bfloat16* __restrict__ hi,
                             __nv_bfloat16* __restrict__ lo, long n) {
    long i = (long)blockIdx.x * blockDim.x + threadIdx.x;
    if (i < n) { __nv_bfloat16 h, l; split1(in[i], h, l); hi[i] = h; lo[i] = l; }
}

// in [K,N] fp32 row-major -> out hi/lo [N,K] bf16 row-major
__global__ void tconv_kernel(const float* __restrict__ in,
                             __nv_bfloat16* __restrict__ hi,
                             __nv_bfloat16* __restrict__ lo, int K, int N) {
    int i = blockIdx.x * blockDim.x + threadIdx.x;
    if (i < K * N) {
        int n = i / K, k = i - n * K;
        __nv_bfloat16 h, l; split1(in[(size_t)k * N + n], h, l);
        hi[(size_t)n * K + k] = h; lo[(size_t)n * K + k] = l;
    }
}

// ---------------- fp32 SGEMM (embeddings + small precompute) ----------------
__global__ void __launch_bounds__(256) sgemm_kernel(
    const float* __restrict__ A, int lda,
    const float* __restrict__ B, int ldb,
    float* __restrict__ C, int ldc,
    int M, int N, int K,
    const float* __restrict__ bias,
    const int* __restrict__ perm)
{
    const int BM = 128, BN = 128, BK = 8;
    __shared__ float As[BK][BM];
    __shared__ float Bs[BK][BN];
    int tid = threadIdx.x;
    int brow = blockIdx.y, bcol = blockIdx.x;
    int aRow = tid >> 1, aCol4 = (tid & 1) * 4;
    int bRow = tid >> 5, bCol4 = (tid & 31) * 4;
    int tr = (tid >> 4) * 8, tc = (tid & 15) * 8;
    float acc[8][8];
#pragma unroll
    for (int i = 0; i < 8; i++)
#pragma unroll
        for (int j = 0; j < 8; j++) acc[i][j] = 0.f;
    int gArow = brow * BM + aRow;
    bool aValid = gArow < M;
    long arow_idx = 0;
    if (aValid) arow_idx = perm ? (long)perm[gArow] : (long)gArow;
    const float* Aptr = A + arow_idx * (long)lda + aCol4;
    const float* Bptr = B + (long)bRow * ldb + (long)bcol * BN + bCol4;
    for (int k0 = 0; k0 < K; k0 += BK) {
        float4 av = aValid ? *(const float4*)(Aptr + k0) : make_float4(0.f, 0.f, 0.f, 0.f);
        float4 bv = *(const float4*)(Bptr + (long)k0 * ldb);
        As[aCol4 + 0][aRow] = av.x; As[aCol4 + 1][aRow] = av.y;
        As[aCol4 + 2][aRow] = av.z; As[aCol4 + 3][aRow] = av.w;
        *(float4*)&Bs[bRow][bCol4] = bv;
        __syncthreads();
#pragma unroll
        for (int kk = 0; kk < BK; kk++) {
            float ar[8], br[8];
#pragma unroll
            for (int i = 0; i < 8; i++) ar[i] = As[kk][tr + i];
#pragma unroll
            for (int j = 0; j < 8; j++) br[j] = Bs[kk][tc + j];
#pragma unroll
            for (int i = 0; i < 8; i++)
#pragma unroll
                for (int j = 0; j < 8; j++)
                    acc[i][j] = fmaf(ar[i], br[j], acc[i][j]);
        }
        __syncthreads();
    }
#pragma unroll
    for (int i = 0; i < 8; i++) {
        int row = brow * BM + tr + i;
        if (row < M) {
#pragma unroll
            for (int j = 0; j < 8; j += 4) {
                int col = bcol * BN + tc + j;
                float4 v;
                v.x = acc[i][j + 0] + (bias ? bias[col + 0] : 0.f);
                v.y = acc[i][j + 1] + (bias ? bias[col + 1] : 0.f);
                v.z = acc[i][j + 2] + (bias ? bias[col + 2] : 0.f);
                v.w = acc[i][j + 3] + (bias ? bias[col + 3] : 0.f);
                *(float4*)&C[(long)row * ldc + col] = v;
            }
        }
    }
}

// ---------------- small helper kernels ----------------
__global__ void count_kernel(const int* __restrict__ dst, int n) {
    int i = blockIdx.x * blockDim.x + threadIdx.x;
    if (i < n) atomicAdd(&d_deg[dst[i]], 1);
}

__global__ void scan_kernel() {
    __shared__ int sh[1024];
    __shared__ int carry;
    if (threadIdx.x == 0) carry = 0;
    __syncthreads();
    for (int base = 0; base < NN; base += 1024) {
        int i = base + (int)threadIdx.x;
        int v = (i < NN) ? d_deg[i] : 0;
        sh[threadIdx.x] = v;
        __syncthreads();
        for (int off = 1; off < 1024; off <<= 1) {
            int t = (threadIdx.x >= (unsigned)off) ? sh[threadIdx.x - off] : 0;
            __syncthreads();
            sh[threadIdx.x] += t;
            __syncthreads();
        }
        if (i < NN) d_offs[i] = carry + sh[threadIdx.x] - v;
        __syncthreads();
        if (threadIdx.x == 1023) carry += sh[1023];
        __syncthreads();
    }
    if (threadIdx.x == 0) d_offs[NN] = carry;
}

__global__ void scatter_kernel(const int* __restrict__ src, const int* __restrict__ dst, int n) {
    int i = blockIdx.x * blockDim.x + threadIdx.x;
    if (i < n) {
        int pos = atomicAdd(&d_cnt[dst[i]], 1);
        d_perm[pos] = i;
        d_srcp[pos] = src[i];
    }
}

// gather permuted raw edge attrs (CSR order), 16 floats per edge
__global__ void gather_eattr_kernel(const float* __restrict__ ea) {
    int i = blockIdx.x * blockDim.x + threadIdx.x;
    if (i < EE) {
        int e = d_perm[i];
        float4* dst = (float4*)(d_eap + (size_t)i * EIN);
        const float4* s = (const float4*)(ea + (size_t)e * EIN);
        dst[0] = s[0]; dst[1] = s[1]; dst[2] = s[2]; dst[3] = s[3];
    }
}

__global__ void logdeg_sum_kernel() {
    __shared__ float sh[256];
    float s = 0.f;
    for (int i = blockIdx.x * blockDim.x + threadIdx.x; i < NN; i += gridDim.x * blockDim.x)
        s += log1pf((float)d_deg[i]);
    sh[threadIdx.x] = s;
    __syncthreads();
    for (int off = 128; off > 0; off >>= 1) {
        if (threadIdx.x < (unsigned)off) sh[threadIdx.x] += sh[threadIdx.x + off];
        __syncthreads();
    }
    if (threadIdx.x == 0) atomicAdd(&d_avg[0], sh[0]);
}

__global__ void scalers_kernel() {
    int i = blockIdx.x * blockDim.x + threadIdx.x;
    if (i < NN) {
        float avg  = d_avg[0] / (float)NN;
        float degc = fmaxf((float)d_deg[i], 1.f);
        float l    = logf(degc + 1.f);
        d_amp[i] = l / avg;
        d_att[i] = avg / l;
    }
}

__global__ void vecmat_kernel(const float* __restrict__ v, const float* __restrict__ W, int ldw,
                              const float* __restrict__ badd, float* __restrict__ out) {
    int c = threadIdx.x;
    float s = 0.f;
    for (int j = 0; j < HH; j++) s = fmaf(v[j], W[j * ldw + c], s);
    out[c] = s + badd[c];
}

// segmented aggregation with fused rank-16 edge message.
// m[c] = hd[c] + t[c] + hs[src][c] + sum_{k<16} eattr_p[r][k]*S[k][c]  (all fp32)
__global__ void agg_kernel(const float* __restrict__ S, const float* __restrict__ t) {
    int node = blockIdx.x;
    int c = threadIdx.x;
    float Sreg[16];
#pragma unroll
    for (int k = 0; k < 16; k++) Sreg[k] = S[k * HH + c];   // coalesced
    int s = d_offs[node], e = d_offs[node + 1];
    float hd = d_cmb[(size_t)node * 384 + c] + t[c];
    float sum = 0.f, ss = 0.f, mn = INFINITY, mx = -INFINITY;
    for (int r = s; r < e; r++) {
        int sp = d_srcp[r];
        const float4* ea = (const float4*)(d_eap + (size_t)r * EIN);
        float4 e0 = ea[0], e1 = ea[1], e2 = ea[2], e3 = ea[3];
        float v = hd + d_cmb[(size_t)sp * 384 + 128 + c];
        v = fmaf(e0.x, Sreg[0],  v); v = fmaf(e0.y, Sreg[1],  v);
        v = fmaf(e0.z, Sreg[2],  v); v = fmaf(e0.w, Sreg[3],  v);
        v = fmaf(e1.x, Sreg[4],  v); v = fmaf(e1.y, Sreg[5],  v);
        v = fmaf(e1.z, Sreg[6],  v); v = fmaf(e1.w, Sreg[7],  v);
        v = fmaf(e2.x, Sreg[8],  v); v = fmaf(e2.y, Sreg[9],  v);
        v = fmaf(e2.z, Sreg[10], v); v = fmaf(e2.w, Sreg[11], v);
        v = fmaf(e3.x, Sreg[12], v); v = fmaf(e3.y, Sreg[13], v);
        v = fmaf(e3.z, Sreg[14], v); v = fmaf(e3.w, Sreg[15], v);
        sum += v;
        ss  = fmaf(v, v, ss);
        mn  = fminf(mn, v);
        mx  = fmaxf(mx, v);
    }
    float deg  = (float)(e - s);
    float degc = fmaxf(deg, 1.f);
    float mean = sum / degc;
    float var  = ss / degc - mean * mean;
    float sd   = sqrtf(fmaxf(var, 0.f) + 1e-5f);
    if (e == s) { mn = 0.f; mx = 0.f; }
    size_t o = (size_t)node * 512;
    __nv_bfloat16 h, l;
    split1(mean, h, l); d_agh[o +       c] = h; d_agl[o +       c] = l;
    split1(mn,   h, l); d_agh[o + 128 + c] = h; d_agl[o + 128 + c] = l;
    split1(mx,   h, l); d_agh[o + 256 + c] = h; d_agl[o + 256 + c] = l;
    split1(sd,   h, l); d_agh[o + 384 + c] = h; d_agl[o + 384 + c] = l;
}

// h_next = relu(z + y0 + amp*y1 + att*y2 + b2); writes fp32 + bf16 split
__global__ void combine_kernel(const float* __restrict__ b2, float* __restrict__ hout,
                               __nv_bfloat16* __restrict__ hh, __nv_bfloat16* __restrict__ hl) {
    int i = blockIdx.x * blockDim.x + threadIdx.x;
    if (i >= NN * HH) return;
    int node = i >> 7, c = i & 127;
    size_t yo = (size_t)node * 384;
    float v = d_cmb[(size_t)node * 384 + 256 + c] + d_y[yo + c]
            + d_amp[node] * d_y[yo + 128 + c]
            + d_att[node] * d_y[yo + 256 + c] + b2[c];
    v = fmaxf(v, 0.f);
    hout[i] = v;
    __nv_bfloat16 h, l; split1(v, h, l);
    hh[i] = h; hl[i] = l;
}

__global__ void pool_kernel(const float* __restrict__ h, const int* __restrict__ batch) {
    int i = blockIdx.x * blockDim.x + threadIdx.x;
    if (i >= NN * HH) return;
    int node = i >> 7, c = i & 127;
    atomicAdd(&d_g[batch[node] * HH + c], h[i]);
}

__global__ void head_kernel(const float* __restrict__ W, const float* __restrict__ b,
                            float* __restrict__ out) {
    __shared__ float sh[HH];
    sh[threadIdx.x] = d_g[blockIdx.x * HH + threadIdx.x];
    __syncthreads();
    if (threadIdx.x < OUTC) {
        float s = b[threadIdx.x];
        for (int k = 0; k < HH; k++) s = fmaf(sh[k], W[k * OUTC + threadIdx.x], s);
        out[blockIdx.x * OUTC + threadIdx.x] = s;
    }
}

// ---------------- host orchestration ----------------
static void gemm(const float* A, int lda, const float* B, int ldb, float* C, int ldc,
                 int M, int N, int K, const float* bias, const int* perm) {
    dim3 grid(N / 128, (M + 127) / 128);
    sgemm_kernel<<<grid, 256>>>(A, lda, B, ldb, C, ldc, M, N, K, bias, perm);
}

static void tgemm(const __nv_bfloat16* Ah, const __nv_bfloat16* Al,
                  const __nv_bfloat16* Bh, const __nv_bfloat16* Bl,
                  float* C, int ldc, int M, int N, int K, const float* bias) {
    dim3 grid((M + 127) / 128, N / 128);
    hmma_kernel<<<grid, 256, TSMEM>>>(Ah, Al, Bh, Bl, C, ldc, M, K, bias);
}

template <typename T>
static T* sym(const void* symbol) {
    void* p = nullptr;
    cudaGetSymbolAddress(&p, symbol);
    return (T*)p;
}

extern "C" void kernel_launch(void* const* d_in, const int* in_sizes, int n_in,
                              void* d_out, int out_size) {
    const float* x     = (const float*)d_in[0];
    const float* eattr = (const float*)d_in[1];
    const int*   src   = (const int*)  d_in[2];
    const int*   dst   = (const int*)  d_in[3];
    const int*   batch = (const int*)  d_in[4];
    const float* nW    = (const float*)d_in[5];
    const float* nb    = (const float*)d_in[6];
    const float* eW    = (const float*)d_in[7];
    const float* eb    = (const float*)d_in[8];
    const float* encW  = (const float*)d_in[9];
    const float* encb  = (const float*)d_in[10];
    const float* preW  = (const float*)d_in[11];
    const float* preb  = (const float*)d_in[12];
    const float* postW = (const float*)d_in[13];
    const float* postb = (const float*)d_in[14];
    const float* linW  = (const float*)d_in[15];
    const float* linb  = (const float*)d_in[16];
    const float* headW = (const float*)d_in[17];
    const float* headb = (const float*)d_in[18];
    float* out = (float*)d_out;

    float* cmb  = sym<float>(d_cmb);
    __nv_bfloat16* agh = sym<__nv_bfloat16>(d_agh);
    __nv_bfloat16* agl = sym<__nv_bfloat16>(d_agl);
    float* y    = sym<float>(d_y);
    float* h0   = sym<float>(d_h0);
    float* h1   = sym<float>(d_h1);
    __nv_bfloat16* hh[2] = { sym<__nv_bfloat16>(d_hh0), sym<__nv_bfloat16>(d_hh1) };
    __nv_bfloat16* hl[2] = { sym<__nv_bfloat16>(d_hl0), sym<__nv_bfloat16>(d_hl1) };
    int*   deg  = sym<int>(d_deg);
    int*   offs = sym<int>(d_offs);
    int*   cnt  = sym<int>(d_cnt);
    float* avg  = sym<float>(d_avg);
    float* S    = sym<float>(d_S);
    float* T1   = sym<float>(d_T1);
    float* u    = sym<float>(d_u);
    float* tl   = sym<float>(d_tl);
    float* Qcat = sym<float>(d_Qcat);
    float* Q0   = sym<float>(d_Q0);
    float* b2   = sym<float>(d_b2);
    float* g    = sym<float>(d_g);
    __nv_bfloat16* Wch = sym<__nv_bfloat16>(d_Wch); __nv_bfloat16* Wcl = sym<__nv_bfloat16>(d_Wcl);
    __nv_bfloat16* Qch = sym<__nv_bfloat16>(d_Qch); __nv_bfloat16* Qcl = sym<__nv_bfloat16>(d_Qcl);

    cudaFuncSetAttribute(hmma_kernel, cudaFuncAttributeMaxDynamicSharedMemorySize, TSMEM);

    const int TPB = 256;

    // ---- graph structure ----
    cudaMemsetAsync(deg, 0, NN * sizeof(int), 0);
    cudaMemsetAsync(avg, 0, sizeof(float), 0);
    count_kernel<<<(EE + TPB - 1) / TPB, TPB>>>(dst, EE);
    scan_kernel<<<1, 1024>>>();
    cudaMemcpyAsync(cnt, offs, NN * sizeof(int), cudaMemcpyDeviceToDevice, 0);
    scatter_kernel<<<(EE + TPB - 1) / TPB, TPB>>>(src, dst, EE);
    gather_eattr_kernel<<<(EE + TPB - 1) / TPB, TPB>>>(eattr);
    logdeg_sum_kernel<<<256, 256>>>();
    scalers_kernel<<<(NN + TPB - 1) / TPB, TPB>>>();

    // ---- node embedding (fp32) + split ----
    gemm(x, FIN, nW, HH, h0, HH, NN, HH, FIN, nb, nullptr);
    split_kernel<<<(int)(((long)NN * HH + TPB - 1) / TPB), TPB>>>(h0, hh[0], hl[0], (long)NN * HH);

    // ---- per-layer weight precompute ----
    for (int l = 0; l < LL; l++) {
        const float* Wenc  = encW + (size_t)l * HH * HH;
        const float* Wpre2 = preW + (size_t)l * 3 * HH * HH + 2 * HH * HH;
        // S_l = eW @ Wenc @ Wpre2  [16,128]
        gemm(eW, HH, Wenc, HH, T1, HH, EIN, HH, HH, nullptr, nullptr);
        gemm(T1, HH, Wpre2, HH, S + (size_t)l * EIN * HH, HH, EIN, HH, HH, nullptr, nullptr);
        // t_l = (eb@Wenc + encb) @ Wpre2 + preb
        vecmat_kernel<<<1, HH>>>(eb, Wenc, HH, encb + l * HH, u);
        vecmat_kernel<<<1, HH>>>(u, Wpre2, HH, preb + l * HH, tl + l * HH);

        const float* Pl  = postW + (size_t)l * 13 * HH * HH;
        const float* lin = linW + (size_t)l * HH * HH;
        for (int q = 0; q < 3; q++) {
            gemm(Pl + (size_t)(HH + q * 4 * HH) * HH, HH, lin, HH,
                 Qcat + (size_t)l * 4 * HH * 3 * HH + q * HH, 3 * HH,
                 4 * HH, HH, HH, nullptr, nullptr);
        }
        gemm(Pl, HH, lin, HH, Q0 + (size_t)l * HH * HH, HH, HH, HH, HH, nullptr, nullptr);
        vecmat_kernel<<<1, HH>>>(postb + l * HH, lin, HH, linb + l * HH, b2 + l * HH);

        // combined node weights: rows 0-127 = W0^T, 128-255 = W1^T, 256-383 = Q0^T
        int nblk = (HH * HH + TPB - 1) / TPB;
        size_t co = (size_t)l * 3 * HH * HH;
        tconv_kernel<<<nblk, TPB>>>(preW + (size_t)l * 3 * HH * HH,
                                    Wch + co, Wcl + co, HH, HH);
        tconv_kernel<<<nblk, TPB>>>(preW + (size_t)l * 3 * HH * HH + HH * HH,
                                    Wch + co + HH * HH, Wcl + co + HH * HH, HH, HH);
        tconv_kernel<<<nblk, TPB>>>(Q0 + (size_t)l * HH * HH,
                                    Wch + co + 2 * HH * HH, Wcl + co + 2 * HH * HH, HH, HH);
        int nblk2 = (4 * HH * 3 * HH + TPB - 1) / TPB;
        tconv_kernel<<<nblk2, TPB>>>(Qcat + (size_t)l * 4 * HH * 3 * HH,
                                     Qch + (size_t)l * 3 * HH * 4 * HH,
                                     Qcl + (size_t)l * 3 * HH * 4 * HH, 4 * HH, 3 * HH);
    }

    // ---- layers ----
    float* hcur = h0;
    float* hnext = h1;
    int cb = 0;
    for (int l = 0; l < LL; l++) {
        // cmb = h @ [W0 | W1 | Q0]  -> [hd|hs|z], N=384
        tgemm(hh[cb], hl[cb], Wch + (size_t)l * 3 * HH * HH, Wcl + (size_t)l * 3 * HH * HH,
              cmb, 3 * HH, NN, 3 * HH, HH, nullptr);
        // segmented aggregation with fused rank-16 edge message -> agg splits [N,512]
        agg_kernel<<<NN, HH>>>(S + (size_t)l * EIN * HH, tl + l * HH);
        // y = agg @ Qcat_l  [N,384]
        tgemm(agh, agl, Qch + (size_t)l * 3 * HH * 4 * HH, Qcl + (size_t)l * 3 * HH * 4 * HH,
              y, 3 * HH, NN, 3 * HH, 4 * HH, nullptr);
        // combine -> hnext fp32 + splits
        combine_kernel<<<(NN * HH + TPB - 1) / TPB, TPB>>>(b2 + l * HH, hnext,
                                                           hh[cb ^ 1], hl[cb ^ 1]);
        float* t = hcur; hcur = hnext; hnext = t;
        cb ^= 1;
    }

    // ---- pool + head ----
    cudaMemsetAsync(g, 0, GG * HH * sizeof(float), 0);
    pool_kernel<<<(NN * HH + TPB - 1) / TPB, TPB>>>(hcur, batch);
    head_kernel<<<GG, HH>>>(headW, headb, out);
}